// round 1
// baseline (speedup 1.0000x reference)
#include <cuda_runtime.h>
#include <math.h>

#define SEQ  4096
#define DIN  1024
#define DOUT 1024

// Scratch (alloc-free rule: __device__ globals)
__device__ float g_Q[(size_t)SEQ * DOUT];
__device__ float g_K[(size_t)SEQ * DOUT];
__device__ float g_V[(size_t)SEQ * DOUT];
__device__ float g_S[(size_t)SEQ * SEQ];   // 64 MB scores / probs

// ---------------------------------------------------------------------------
// Tiled SGEMM: C[M,N] = alpha * A[M,K] @ op(B)
//   BT=false: B is [K,N] row-major (NN)
//   BT=true : B is [N,K] row-major, compute A @ B^T (NT)
// Block tile 128x128, k-tile 8, 256 threads, 8x8 per-thread micro-tile.
// All dims are multiples of 128 here, so no bounds checks.
// ---------------------------------------------------------------------------
template <bool BT>
__global__ void __launch_bounds__(256, 2)
sgemm_kernel(const float* __restrict__ A, const float* __restrict__ B,
             float* __restrict__ C, int M, int N, int K, float alpha)
{
    __shared__ float As[8][132];   // padded to reduce scatter-store conflicts
    __shared__ float Bs[8][132];

    const int tid = threadIdx.x;
    const int tx  = tid & 15;      // 0..15  -> column micro-tile
    const int ty  = tid >> 4;      // 0..15  -> row micro-tile
    const int rowBase = blockIdx.y * 128;
    const int colBase = blockIdx.x * 128;

    // global-load indexing
    const int ldRow = tid >> 1;          // 0..127
    const int ldK4  = (tid & 1) * 4;     // 0 or 4
    const int ldBk  = tid >> 5;          // 0..7   (NN B load)
    const int ldBn4 = (tid & 31) * 4;    // 0..124 (NN B load)

    float acc[8][8];
#pragma unroll
    for (int i = 0; i < 8; i++)
#pragma unroll
        for (int j = 0; j < 8; j++) acc[i][j] = 0.0f;

    for (int k0 = 0; k0 < K; k0 += 8) {
        // --- load A tile (128 rows x 8 k), transpose into As[k][row] ---
        {
            const float4 a4 = *(const float4*)(A + (size_t)(rowBase + ldRow) * K + k0 + ldK4);
            As[ldK4 + 0][ldRow] = a4.x;
            As[ldK4 + 1][ldRow] = a4.y;
            As[ldK4 + 2][ldRow] = a4.z;
            As[ldK4 + 3][ldRow] = a4.w;
        }
        // --- load B tile into Bs[k][n] ---
        if (BT) {
            const float4 b4 = *(const float4*)(B + (size_t)(colBase + ldRow) * K + k0 + ldK4);
            Bs[ldK4 + 0][ldRow] = b4.x;
            Bs[ldK4 + 1][ldRow] = b4.y;
            Bs[ldK4 + 2][ldRow] = b4.z;
            Bs[ldK4 + 3][ldRow] = b4.w;
        } else {
            const float4 b4 = *(const float4*)(B + (size_t)(k0 + ldBk) * N + colBase + ldBn4);
            Bs[ldBk][ldBn4 + 0] = b4.x;
            Bs[ldBk][ldBn4 + 1] = b4.y;
            Bs[ldBk][ldBn4 + 2] = b4.z;
            Bs[ldBk][ldBn4 + 3] = b4.w;
        }
        __syncthreads();

#pragma unroll
        for (int kk = 0; kk < 8; kk++) {
            float a[8], b[8];
            *(float4*)(a + 0) = *(const float4*)&As[kk][ty * 8 + 0];
            *(float4*)(a + 4) = *(const float4*)&As[kk][ty * 8 + 4];
            *(float4*)(b + 0) = *(const float4*)&Bs[kk][tx * 8 + 0];
            *(float4*)(b + 4) = *(const float4*)&Bs[kk][tx * 8 + 4];
#pragma unroll
            for (int i = 0; i < 8; i++)
#pragma unroll
                for (int j = 0; j < 8; j++)
                    acc[i][j] = fmaf(a[i], b[j], acc[i][j]);
        }
        __syncthreads();
    }

    // --- store ---
#pragma unroll
    for (int i = 0; i < 8; i++) {
        const size_t r = (size_t)(rowBase + ty * 8 + i);
        float4 o0, o1;
        o0.x = alpha * acc[i][0]; o0.y = alpha * acc[i][1];
        o0.z = alpha * acc[i][2]; o0.w = alpha * acc[i][3];
        o1.x = alpha * acc[i][4]; o1.y = alpha * acc[i][5];
        o1.z = alpha * acc[i][6]; o1.w = alpha * acc[i][7];
        *(float4*)(C + r * N + colBase + tx * 8 + 0) = o0;
        *(float4*)(C + r * N + colBase + tx * 8 + 4) = o1;
    }
}

// ---------------------------------------------------------------------------
// Row softmax over S[4096][4096], in place. One block (256 threads) per row.
// ---------------------------------------------------------------------------
__global__ void __launch_bounds__(256)
softmax_kernel(float* __restrict__ S)
{
    __shared__ float red[256];
    const int tid = threadIdx.x;
    float* p = S + (size_t)blockIdx.x * SEQ;

    // pass 1: row max
    float m = -INFINITY;
    for (int c = tid * 4; c < SEQ; c += 256 * 4) {
        const float4 v = *(const float4*)(p + c);
        m = fmaxf(m, fmaxf(fmaxf(v.x, v.y), fmaxf(v.z, v.w)));
    }
    red[tid] = m;
    __syncthreads();
    for (int s = 128; s > 0; s >>= 1) {
        if (tid < s) red[tid] = fmaxf(red[tid], red[tid + s]);
        __syncthreads();
    }
    m = red[0];
    __syncthreads();

    // pass 2: exp + sum
    float sum = 0.0f;
    for (int c = tid * 4; c < SEQ; c += 256 * 4) {
        float4 v = *(const float4*)(p + c);
        v.x = expf(v.x - m);
        v.y = expf(v.y - m);
        v.z = expf(v.z - m);
        v.w = expf(v.w - m);
        *(float4*)(p + c) = v;
        sum += v.x + v.y + v.z + v.w;
    }
    red[tid] = sum;
    __syncthreads();
    for (int s = 128; s > 0; s >>= 1) {
        if (tid < s) red[tid] += red[tid + s];
        __syncthreads();
    }
    const float inv = 1.0f / red[0];
    __syncthreads();

    // pass 3: normalize
    for (int c = tid * 4; c < SEQ; c += 256 * 4) {
        float4 v = *(const float4*)(p + c);
        v.x *= inv; v.y *= inv; v.z *= inv; v.w *= inv;
        *(float4*)(p + c) = v;
    }
}

// ---------------------------------------------------------------------------
extern "C" void kernel_launch(void* const* d_in, const int* in_sizes, int n_in,
                              void* d_out, int out_size)
{
    const float* input = (const float*)d_in[0];
    const float* Wq    = (const float*)d_in[1];
    const float* Wk    = (const float*)d_in[2];
    const float* Wv    = (const float*)d_in[3];
    float*       out   = (float*)d_out;

    float *Q, *K, *V, *S;
    cudaGetSymbolAddress((void**)&Q, g_Q);
    cudaGetSymbolAddress((void**)&K, g_K);
    cudaGetSymbolAddress((void**)&V, g_V);
    cudaGetSymbolAddress((void**)&S, g_S);

    const float scale = 1.0f / 32.0f;   // 1/sqrt(1024)

    // Q/K/V projections: [4096,1024] = [4096,1024] @ [1024,1024]
    dim3 gProj(DOUT / 128, SEQ / 128);
    sgemm_kernel<false><<<gProj, 256>>>(input, Wq, Q, SEQ, DOUT, DIN, 1.0f);
    sgemm_kernel<false><<<gProj, 256>>>(input, Wk, K, SEQ, DOUT, DIN, 1.0f);
    sgemm_kernel<false><<<gProj, 256>>>(input, Wv, V, SEQ, DOUT, DIN, 1.0f);

    // scores: S = (Q @ K^T) * scale  -> [4096,4096]
    dim3 gScores(SEQ / 128, SEQ / 128);
    sgemm_kernel<true><<<gScores, 256>>>(Q, K, S, SEQ, SEQ, DOUT, scale);

    // softmax rows in place
    softmax_kernel<<<SEQ, 256>>>(S);

    // out = P @ V -> [4096,1024]
    sgemm_kernel<false><<<gProj, 256>>>(S, V, out, SEQ, DOUT, SEQ, 1.0f);
}

// round 4
// speedup vs baseline: 1.6393x; 1.6393x over previous
#include <cuda_runtime.h>
#include <math.h>
#include <stdint.h>

#define SEQ  4096
#define DIN  1024
#define DOUT 1024

// ---------------- scratch (__device__ globals, alloc-free rule) ----------------
__device__ float g_inCat[(size_t)SEQ * (3 * DIN)];     // [in_hi | in_hi | in_lo]
__device__ float g_WqCT[(size_t)DOUT * (3 * DIN)];     // W^T cat: [hi | lo | hi]
__device__ float g_WkCT[(size_t)DOUT * (3 * DIN)];
__device__ float g_WvCT[(size_t)DOUT * (3 * DIN)];
__device__ float g_Q[(size_t)SEQ * DOUT];              // fp32-accurate
__device__ float g_K[(size_t)SEQ * DOUT];
__device__ float g_V[(size_t)SEQ * DOUT];
__device__ float g_QCat[(size_t)SEQ * (3 * DOUT)];     // [Qhi | Qhi | Qlo]
__device__ float g_KCat[(size_t)SEQ * (3 * DOUT)];     // [Khi | Klo | Khi]
__device__ float g_VT[(size_t)DOUT * SEQ];             // rna(V^T)
__device__ float g_S[(size_t)SEQ * SEQ];               // scores / probs (64MB)

// ---------------- helpers ----------------
__device__ __forceinline__ uint32_t smem_u32(const void* p) {
    uint32_t a;
    asm("{ .reg .u64 t; cvta.to.shared.u64 t, %1; cvt.u32.u64 %0, t; }" : "=r"(a) : "l"(p));
    return a;
}
__device__ __forceinline__ float rna_tf32(float x) {
    float y;
    asm("cvt.rna.tf32.f32 %0, %1;" : "=f"(y) : "f"(x));
    return y;
}
#define CP_ASYNC16(saddr, gaddr) \
    asm volatile("cp.async.cg.shared.global [%0], [%1], 16;" :: "r"(saddr), "l"(gaddr))
#define CP_COMMIT() asm volatile("cp.async.commit_group;" ::: "memory")
#define CP_WAIT1()  asm volatile("cp.async.wait_group 1;" ::: "memory")

// mma.sync m16n8k8 tf32 (family-common; compiles for base sm_103 target)
__device__ __forceinline__ void mma_tf32(float* d,
                                         uint32_t a0, uint32_t a1, uint32_t a2, uint32_t a3,
                                         uint32_t b0, uint32_t b1) {
    asm volatile("mma.sync.aligned.m16n8k8.row.col.f32.tf32.tf32.f32 "
                 "{%0,%1,%2,%3}, {%4,%5,%6,%7}, {%8,%9}, {%0,%1,%2,%3};"
                 : "+f"(d[0]), "+f"(d[1]), "+f"(d[2]), "+f"(d[3])
                 : "r"(a0), "r"(a1), "r"(a2), "r"(a3), "r"(b0), "r"(b1));
}

// ---------------------------------------------------------------------------
// tf32 mma.sync GEMM: C[M,Ntot] = alpha * A[M,Kd] @ B[Ntot,Kd]^T (both K-major)
// CTA 128x128x32, 8 warps (2Mx4N), warp tile 64x32 (4x4 m16n8k8 frags).
// Padded smem stride 36, 2-stage cp.async double buffer, 2 CTAs/SM.
// ---------------------------------------------------------------------------
#define PAD_STRIDE 36
#define OP_BYTES   (128 * PAD_STRIDE * 4)
#define STAGE_BYTES (2 * OP_BYTES)
#define NSTAGE 2

__global__ void __launch_bounds__(256, 2)
tf32_gemm(const float* __restrict__ A, const float* __restrict__ B,
          float* __restrict__ C, int M, int Ntot, int Kd, float alpha)
{
    extern __shared__ float smf[];
    const uint32_t sbase = smem_u32(smf);

    const int tid  = threadIdx.x;
    const int wid  = tid >> 5;
    const int lane = tid & 31;
    const int warpM = wid >> 2;
    const int warpN = wid & 3;
    const int gID  = lane >> 2;
    const int tig  = lane & 3;
    const int rowBase = blockIdx.y * 128;
    const int colBase = blockIdx.x * 128;

    const int ldRow0 = tid >> 3;
    const int ldSeg  = tid & 7;

    auto load_stage = [&](int st, int k0) {
        const uint32_t sA = sbase + st * STAGE_BYTES;
        const uint32_t sB = sA + OP_BYTES;
#pragma unroll
        for (int i = 0; i < 4; i++) {
            const int row = ldRow0 + i * 32;
            CP_ASYNC16(sA + (row * PAD_STRIDE + ldSeg * 4) * 4,
                       A + (size_t)(rowBase + row) * Kd + k0 + ldSeg * 4);
        }
#pragma unroll
        for (int i = 0; i < 4; i++) {
            const int row = ldRow0 + i * 32;
            CP_ASYNC16(sB + (row * PAD_STRIDE + ldSeg * 4) * 4,
                       B + (size_t)(colBase + row) * Kd + k0 + ldSeg * 4);
        }
    };

    float acc[4][4][4];
#pragma unroll
    for (int i = 0; i < 4; i++)
#pragma unroll
        for (int j = 0; j < 4; j++)
#pragma unroll
            for (int r = 0; r < 4; r++) acc[i][j][r] = 0.0f;

    const int NITER = Kd >> 5;

    load_stage(0, 0);
    CP_COMMIT();
    if (NITER > 1) load_stage(1, 32);
    CP_COMMIT();

    for (int j = 0; j < NITER; j++) {
        CP_WAIT1();
        __syncthreads();

        const float* fA = (const float*)(smf) + ((j & 1) * STAGE_BYTES) / 4;
        const float* fB = fA + OP_BYTES / 4;

#pragma unroll
        for (int s = 0; s < 4; s++) {
            uint32_t af[4][4];
#pragma unroll
            for (int i = 0; i < 4; i++) {
                const int r0 = warpM * 64 + i * 16 + gID;
                const int c0 = s * 8 + tig;
                af[i][0] = __float_as_uint(fA[r0 * PAD_STRIDE + c0]);
                af[i][1] = __float_as_uint(fA[(r0 + 8) * PAD_STRIDE + c0]);
                af[i][2] = __float_as_uint(fA[r0 * PAD_STRIDE + c0 + 4]);
                af[i][3] = __float_as_uint(fA[(r0 + 8) * PAD_STRIDE + c0 + 4]);
            }
            uint32_t bf[4][2];
#pragma unroll
            for (int jn = 0; jn < 4; jn++) {
                const int n0 = warpN * 32 + jn * 8 + gID;
                const int c0 = s * 8 + tig;
                bf[jn][0] = __float_as_uint(fB[n0 * PAD_STRIDE + c0]);
                bf[jn][1] = __float_as_uint(fB[n0 * PAD_STRIDE + c0 + 4]);
            }
#pragma unroll
            for (int i = 0; i < 4; i++)
#pragma unroll
                for (int jn = 0; jn < 4; jn++)
                    mma_tf32(acc[i][jn], af[i][0], af[i][1], af[i][2], af[i][3],
                             bf[jn][0], bf[jn][1]);
        }
        __syncthreads();
        if (j + 2 < NITER) load_stage((j + 2) & 1, (j + 2) * 32);
        CP_COMMIT();
    }

#pragma unroll
    for (int i = 0; i < 4; i++) {
        const int r0 = rowBase + warpM * 64 + i * 16 + gID;
#pragma unroll
        for (int jn = 0; jn < 4; jn++) {
            const int c = colBase + warpN * 32 + jn * 8 + tig * 2;
            float2 lo, hi;
            lo.x = alpha * acc[i][jn][0]; lo.y = alpha * acc[i][jn][1];
            hi.x = alpha * acc[i][jn][2]; hi.y = alpha * acc[i][jn][3];
            *(float2*)(C + (size_t)r0 * Ntot + c)       = lo;
            *(float2*)(C + (size_t)(r0 + 8) * Ntot + c) = hi;
        }
    }
}

// ---------------------------------------------------------------------------
// split-cat: in[R,C] fp32 -> out[R,3C]; hi copies + lo placed per mode.
//   modeB=0 (A operand): [hi | hi | lo]
//   modeB=1 (B operand): [hi | lo | hi]
// ---------------------------------------------------------------------------
__global__ void __launch_bounds__(256)
split_cat(const float* __restrict__ in, float* __restrict__ out, int R, int C, int modeB)
{
    int i = blockIdx.x * 256 + threadIdx.x;           // float4 index
    int n4 = R * C / 4;
    if (i >= n4) return;
    float4 v = ((const float4*)in)[i];
    float4 h, l;
    h.x = rna_tf32(v.x); l.x = rna_tf32(v.x - h.x);
    h.y = rna_tf32(v.y); l.y = rna_tf32(v.y - h.y);
    h.z = rna_tf32(v.z); l.z = rna_tf32(v.z - h.z);
    h.w = rna_tf32(v.w); l.w = rna_tf32(v.w - h.w);
    int e = i * 4;
    int r = e / C, c = e % C;
    float* row = out + (size_t)r * (3 * C) + c;
    if (modeB) {
        *(float4*)(row)         = h;
        *(float4*)(row + C)     = l;
        *(float4*)(row + 2 * C) = h;
    } else {
        *(float4*)(row)         = h;
        *(float4*)(row + C)     = h;
        *(float4*)(row + 2 * C) = l;
    }
}

// ---------------------------------------------------------------------------
// transpose + split-cat (B mode): in W[R,Cc] -> out[Cc, 3R] = [hi | lo | hi] of W^T
// ---------------------------------------------------------------------------
__global__ void __launch_bounds__(256)
transpose_split_cat(const float* __restrict__ in, float* __restrict__ out, int R, int Cc)
{
    __shared__ float t[32][33];
    const int tx = threadIdx.x, ty = threadIdx.y;
    const int cx = blockIdx.x * 32 + tx;
#pragma unroll
    for (int i = 0; i < 4; i++) {
        int r = blockIdx.y * 32 + ty + i * 8;
        t[ty + i * 8][tx] = in[(size_t)r * Cc + cx];
    }
    __syncthreads();
    const int ox = blockIdx.y * 32 + tx;
#pragma unroll
    for (int i = 0; i < 4; i++) {
        int oy = blockIdx.x * 32 + ty + i * 8;
        float v = t[tx][ty + i * 8];
        float h = rna_tf32(v);
        float l = rna_tf32(v - h);
        float* row = out + (size_t)oy * (3 * R) + ox;
        row[0]     = h;
        row[R]     = l;
        row[2 * R] = h;
    }
}

// ---------------------------------------------------------------------------
// plain transpose + rna: V[R,Cc] -> VT[Cc,R]
// ---------------------------------------------------------------------------
__global__ void __launch_bounds__(256)
transpose_rna(const float* __restrict__ in, float* __restrict__ out, int R, int Cc)
{
    __shared__ float t[32][33];
    const int tx = threadIdx.x, ty = threadIdx.y;
    const int cx = blockIdx.x * 32 + tx;
#pragma unroll
    for (int i = 0; i < 4; i++) {
        int r = blockIdx.y * 32 + ty + i * 8;
        t[ty + i * 8][tx] = rna_tf32(in[(size_t)r * Cc + cx]);
    }
    __syncthreads();
    const int ox = blockIdx.y * 32 + tx;
#pragma unroll
    for (int i = 0; i < 4; i++) {
        int oy = blockIdx.x * 32 + ty + i * 8;
        out[(size_t)oy * R + ox] = t[tx][ty + i * 8];
    }
}

// ---------------------------------------------------------------------------
// row softmax, in place; probs rna-rounded (exact tf32 operands for PV GEMM)
// ---------------------------------------------------------------------------
__global__ void __launch_bounds__(256)
softmax_kernel(float* __restrict__ S)
{
    __shared__ float red[256];
    const int tid = threadIdx.x;
    float* p = S + (size_t)blockIdx.x * SEQ;

    float m = -INFINITY;
    for (int c = tid * 4; c < SEQ; c += 1024) {
        const float4 v = *(const float4*)(p + c);
        m = fmaxf(m, fmaxf(fmaxf(v.x, v.y), fmaxf(v.z, v.w)));
    }
    red[tid] = m; __syncthreads();
    for (int s = 128; s > 0; s >>= 1) { if (tid < s) red[tid] = fmaxf(red[tid], red[tid + s]); __syncthreads(); }
    m = red[0]; __syncthreads();

    float sum = 0.0f;
    for (int c = tid * 4; c < SEQ; c += 1024) {
        float4 v = *(const float4*)(p + c);
        v.x = expf(v.x - m); v.y = expf(v.y - m);
        v.z = expf(v.z - m); v.w = expf(v.w - m);
        *(float4*)(p + c) = v;
        sum += v.x + v.y + v.z + v.w;
    }
    red[tid] = sum; __syncthreads();
    for (int s = 128; s > 0; s >>= 1) { if (tid < s) red[tid] += red[tid + s]; __syncthreads(); }
    const float inv = 1.0f / red[0];
    __syncthreads();

    for (int c = tid * 4; c < SEQ; c += 1024) {
        float4 v = *(const float4*)(p + c);
        v.x = rna_tf32(v.x * inv); v.y = rna_tf32(v.y * inv);
        v.z = rna_tf32(v.z * inv); v.w = rna_tf32(v.w * inv);
        *(float4*)(p + c) = v;
    }
}

// ---------------------------------------------------------------------------
extern "C" void kernel_launch(void* const* d_in, const int* in_sizes, int n_in,
                              void* d_out, int out_size)
{
    const float* input = (const float*)d_in[0];
    const float* Wq    = (const float*)d_in[1];
    const float* Wk    = (const float*)d_in[2];
    const float* Wv    = (const float*)d_in[3];
    float*       out   = (float*)d_out;

    float *inCat, *WqCT, *WkCT, *WvCT, *Q, *K, *V, *QCat, *KCat, *VT, *S;
    cudaGetSymbolAddress((void**)&inCat, g_inCat);
    cudaGetSymbolAddress((void**)&WqCT,  g_WqCT);
    cudaGetSymbolAddress((void**)&WkCT,  g_WkCT);
    cudaGetSymbolAddress((void**)&WvCT,  g_WvCT);
    cudaGetSymbolAddress((void**)&Q,     g_Q);
    cudaGetSymbolAddress((void**)&K,     g_K);
    cudaGetSymbolAddress((void**)&V,     g_V);
    cudaGetSymbolAddress((void**)&QCat,  g_QCat);
    cudaGetSymbolAddress((void**)&KCat,  g_KCat);
    cudaGetSymbolAddress((void**)&VT,    g_VT);
    cudaGetSymbolAddress((void**)&S,     g_S);

    const int smem_sz = NSTAGE * STAGE_BYTES;
    cudaFuncSetAttribute(tf32_gemm, cudaFuncAttributeMaxDynamicSharedMemorySize, smem_sz);

    const float scale = 1.0f / 32.0f;   // 1/sqrt(1024)
    dim3 tb(32, 8);

    // ---- stage split operands ----
    split_cat<<<(SEQ * DIN / 4 + 255) / 256, 256>>>(input, inCat, SEQ, DIN, 0);
    transpose_split_cat<<<dim3(DOUT / 32, DIN / 32), tb>>>(Wq, WqCT, DIN, DOUT);
    transpose_split_cat<<<dim3(DOUT / 32, DIN / 32), tb>>>(Wk, WkCT, DIN, DOUT);
    transpose_split_cat<<<dim3(DOUT / 32, DIN / 32), tb>>>(Wv, WvCT, DIN, DOUT);

    // ---- projections via 3xTF32 (K = 3072): fp32-accurate Q, K, V ----
    dim3 gProj(DOUT / 128, SEQ / 128);
    tf32_gemm<<<gProj, 256, smem_sz>>>(inCat, WqCT, Q, SEQ, DOUT, 3 * DIN, 1.0f);
    tf32_gemm<<<gProj, 256, smem_sz>>>(inCat, WkCT, K, SEQ, DOUT, 3 * DIN, 1.0f);
    tf32_gemm<<<gProj, 256, smem_sz>>>(inCat, WvCT, V, SEQ, DOUT, 3 * DIN, 1.0f);

    // ---- split Q, K for 3xTF32 scores ----
    split_cat<<<(SEQ * DOUT / 4 + 255) / 256, 256>>>(Q, QCat, SEQ, DOUT, 0);
    split_cat<<<(SEQ * DOUT / 4 + 255) / 256, 256>>>(K, KCat, SEQ, DOUT, 1);

    // V^T (rna) for PV
    transpose_rna<<<dim3(DOUT / 32, SEQ / 32), tb>>>(V, VT, SEQ, DOUT);

    // ---- scores: S = (Q @ K^T) * scale, 3xTF32 (K = 3072) ----
    dim3 gS(SEQ / 128, SEQ / 128);
    tf32_gemm<<<gS, 256, smem_sz>>>(QCat, KCat, S, SEQ, SEQ, 3 * DOUT, scale);

    softmax_kernel<<<SEQ, 256>>>(S);

    // ---- out = P @ (V^T)^T, single tf32 (rna-rounded operands) ----
    tf32_gemm<<<gProj, 256, smem_sz>>>(S, VT, out, SEQ, DOUT, SEQ, 1.0f);
}

// round 6
// speedup vs baseline: 1.7502x; 1.0676x over previous
#include <cuda_runtime.h>
#include <math.h>
#include <stdint.h>

#define SEQ  4096
#define DIN  1024
#define DOUT 1024

// ---------------- scratch (__device__ globals, alloc-free rule) ----------------
__device__ float g_inCat[(size_t)SEQ * (3 * DIN)];     // [hi | hi | lo] of input
__device__ float g_WqCT[(size_t)DOUT * (3 * DIN)];     // [hi | lo | hi] of Wq^T
__device__ float g_WkCT[(size_t)DOUT * (3 * DIN)];
__device__ float g_WvCT[(size_t)DOUT * (3 * DIN)];
__device__ float g_QCat[(size_t)SEQ * (3 * DOUT)];     // [Qhi | Qhi | Qlo]
__device__ float g_KCat[(size_t)SEQ * (3 * DOUT)];     // [Khi | Klo | Khi]
__device__ float g_V[(size_t)SEQ * DOUT];
__device__ float g_VT[(size_t)DOUT * SEQ];             // rna(V^T)
__device__ float g_S[(size_t)SEQ * SEQ];               // scores / probs (64MB)

// ---------------- helpers ----------------
__device__ __forceinline__ float rna_tf32(float x) {
    float y;
    asm("cvt.rna.tf32.f32 %0, %1;" : "=f"(y) : "f"(x));
    return y;
}
#define CP_ASYNC16(saddr, gaddr) \
    asm volatile("cp.async.cg.shared.global [%0], [%1], 16;" :: "r"(saddr), "l"(gaddr))
#define CP_COMMIT() asm volatile("cp.async.commit_group;" ::: "memory")
#define CP_WAIT1()  asm volatile("cp.async.wait_group 1;" ::: "memory")

__device__ __forceinline__ uint32_t smem_u32(const void* p) {
    uint32_t a;
    asm("{ .reg .u64 t; cvta.to.shared.u64 t, %1; cvt.u32.u64 %0, t; }" : "=r"(a) : "l"(p));
    return a;
}

// mma.sync m16n8k8 tf32 (family-common; compiles for base sm_103 target)
__device__ __forceinline__ void mma_tf32(float* d,
                                         uint32_t a0, uint32_t a1, uint32_t a2, uint32_t a3,
                                         uint32_t b0, uint32_t b1) {
    asm volatile("mma.sync.aligned.m16n8k8.row.col.f32.tf32.tf32.f32 "
                 "{%0,%1,%2,%3}, {%4,%5,%6,%7}, {%8,%9}, {%0,%1,%2,%3};"
                 : "+f"(d[0]), "+f"(d[1]), "+f"(d[2]), "+f"(d[3])
                 : "r"(a0), "r"(a1), "r"(a2), "r"(a3), "r"(b0), "r"(b1));
}

// ---------------------------------------------------------------------------
// tf32 mma.sync GEMM: C = alpha * A[M,K] @ B[N,K]^T  (both K-major, strided)
// CTA 128x128x32, 4 warps (2Mx2N), warp tile 64x64 (4m x 8n m16n8k8).
// Padded smem stride 36, 2-stage cp.async, 2 CTAs/SM, 8-row raster swizzle.
// outMode: 0 plain, 1 split-cat A [hi|hi|lo], 2 split-cat B [hi|lo|hi]
//          (split modes write C with row stride 3*Ntot)
// ---------------------------------------------------------------------------
#define PAD_STRIDE 36
#define OP_BYTES   (128 * PAD_STRIDE * 4)
#define STAGE_BYTES (2 * OP_BYTES)
#define NSTAGE 2

__global__ void __launch_bounds__(128, 2)
tf32_gemm(const float* __restrict__ A, const float* __restrict__ B,
          float* __restrict__ C, int Ntot, int Kd, int lda, int ldb,
          float alpha, int outMode)
{
    extern __shared__ float smf[];
    const uint32_t sbase = smem_u32(smf);

    // ---- 8-row supertile raster swizzle for L2 reuse ----
    const int gx = gridDim.x, gy = gridDim.y;
    const int lin = blockIdx.y * gx + blockIdx.x;
    const int GROUP = 8;
    const int per = GROUP * gx;
    const int g = lin / per;
    const int rem = lin - g * per;
    const int rowsLeft = gy - g * GROUP;
    const int rows = (GROUP < rowsLeft) ? GROUP : rowsLeft;
    const int byi = g * GROUP + rem % rows;
    const int bxi = rem / rows;

    const int tid  = threadIdx.x;
    const int wid  = tid >> 5;
    const int lane = tid & 31;
    const int warpM = wid >> 1;          // 0..1
    const int warpN = wid & 1;           // 0..1
    const int gID  = lane >> 2;          // 0..7
    const int tig  = lane & 3;           // 0..3
    const int rowBase = byi * 128;
    const int colBase = bxi * 128;

    const int ldRow0 = tid >> 3;         // 0..15 (advances +16 per i)
    const int ldSeg  = tid & 7;

    auto load_stage = [&](int st, int k0) {
        const uint32_t sA = sbase + st * STAGE_BYTES;
        const uint32_t sB = sA + OP_BYTES;
#pragma unroll
        for (int i = 0; i < 8; i++) {
            const int row = ldRow0 + i * 16;
            CP_ASYNC16(sA + (row * PAD_STRIDE + ldSeg * 4) * 4,
                       A + (size_t)(rowBase + row) * lda + k0 + ldSeg * 4);
        }
#pragma unroll
        for (int i = 0; i < 8; i++) {
            const int row = ldRow0 + i * 16;
            CP_ASYNC16(sB + (row * PAD_STRIDE + ldSeg * 4) * 4,
                       B + (size_t)(colBase + row) * ldb + k0 + ldSeg * 4);
        }
    };

    float acc[4][8][4];
#pragma unroll
    for (int i = 0; i < 4; i++)
#pragma unroll
        for (int j = 0; j < 8; j++)
#pragma unroll
            for (int r = 0; r < 4; r++) acc[i][j][r] = 0.0f;

    const int NITER = Kd >> 5;

    load_stage(0, 0);
    CP_COMMIT();
    load_stage(1, 32);
    CP_COMMIT();

    for (int j = 0; j < NITER; j++) {
        CP_WAIT1();
        __syncthreads();

        const float* fA = (const float*)(smf) + ((j & 1) * STAGE_BYTES) / 4;
        const float* fB = fA + OP_BYTES / 4;

#pragma unroll
        for (int s = 0; s < 4; s++) {
            uint32_t af[4][4];
#pragma unroll
            for (int i = 0; i < 4; i++) {
                const int r0 = warpM * 64 + i * 16 + gID;
                const int c0 = s * 8 + tig;
                af[i][0] = __float_as_uint(fA[r0 * PAD_STRIDE + c0]);
                af[i][1] = __float_as_uint(fA[(r0 + 8) * PAD_STRIDE + c0]);
                af[i][2] = __float_as_uint(fA[r0 * PAD_STRIDE + c0 + 4]);
                af[i][3] = __float_as_uint(fA[(r0 + 8) * PAD_STRIDE + c0 + 4]);
            }
            uint32_t bf[8][2];
#pragma unroll
            for (int jn = 0; jn < 8; jn++) {
                const int n0 = warpN * 64 + jn * 8 + gID;
                const int c0 = s * 8 + tig;
                bf[jn][0] = __float_as_uint(fB[n0 * PAD_STRIDE + c0]);
                bf[jn][1] = __float_as_uint(fB[n0 * PAD_STRIDE + c0 + 4]);
            }
#pragma unroll
            for (int i = 0; i < 4; i++)
#pragma unroll
                for (int jn = 0; jn < 8; jn++)
                    mma_tf32(acc[i][jn], af[i][0], af[i][1], af[i][2], af[i][3],
                             bf[jn][0], bf[jn][1]);
        }
        __syncthreads();
        if (j + 2 < NITER) load_stage((j + 2) & 1, (j + 2) * 32);
        CP_COMMIT();
    }

    // ---- epilogue ----
#pragma unroll
    for (int i = 0; i < 4; i++) {
        const int r0 = rowBase + warpM * 64 + i * 16 + gID;
#pragma unroll
        for (int jn = 0; jn < 8; jn++) {
            const int c = colBase + warpN * 64 + jn * 8 + tig * 2;
#pragma unroll
            for (int half = 0; half < 2; half++) {
                const int r = r0 + half * 8;
                float2 v;
                v.x = alpha * acc[i][jn][half * 2 + 0];
                v.y = alpha * acc[i][jn][half * 2 + 1];
                if (outMode == 0) {
                    *(float2*)(C + (size_t)r * Ntot + c) = v;
                } else {
                    float2 h, l;
                    h.x = rna_tf32(v.x); l.x = rna_tf32(v.x - h.x);
                    h.y = rna_tf32(v.y); l.y = rna_tf32(v.y - h.y);
                    float* row = C + (size_t)r * (3 * Ntot) + c;
                    if (outMode == 1) {          // A-split: [hi | hi | lo]
                        *(float2*)(row)            = h;
                        *(float2*)(row + Ntot)     = h;
                        *(float2*)(row + 2 * Ntot) = l;
                    } else {                     // B-split: [hi | lo | hi]
                        *(float2*)(row)            = h;
                        *(float2*)(row + Ntot)     = l;
                        *(float2*)(row + 2 * Ntot) = h;
                    }
                }
            }
        }
    }
}

// ---------------------------------------------------------------------------
// split-cat: in[R,C] fp32 -> out[R,3C], A mode [hi|hi|lo]
// ---------------------------------------------------------------------------
__global__ void __launch_bounds__(256)
split_cat(const float* __restrict__ in, float* __restrict__ out, int R, int C)
{
    int i = blockIdx.x * 256 + threadIdx.x;
    int n4 = R * C / 4;
    if (i >= n4) return;
    float4 v = ((const float4*)in)[i];
    float4 h, l;
    h.x = rna_tf32(v.x); l.x = rna_tf32(v.x - h.x);
    h.y = rna_tf32(v.y); l.y = rna_tf32(v.y - h.y);
    h.z = rna_tf32(v.z); l.z = rna_tf32(v.z - h.z);
    h.w = rna_tf32(v.w); l.w = rna_tf32(v.w - h.w);
    int e = i * 4;
    int r = e / C, c = e % C;
    float* row = out + (size_t)r * (3 * C) + c;
    *(float4*)(row)         = h;
    *(float4*)(row + C)     = h;
    *(float4*)(row + 2 * C) = l;
}

// ---------------------------------------------------------------------------
// transpose + split-cat (B mode): W[R,Cc] -> out[Cc,3R] = [hi | lo | hi] of W^T
// ---------------------------------------------------------------------------
__global__ void __launch_bounds__(256)
transpose_split_cat(const float* __restrict__ in, float* __restrict__ out, int R, int Cc)
{
    __shared__ float t[32][33];
    const int tx = threadIdx.x, ty = threadIdx.y;
    const int cx = blockIdx.x * 32 + tx;
#pragma unroll
    for (int i = 0; i < 4; i++) {
        int r = blockIdx.y * 32 + ty + i * 8;
        t[ty + i * 8][tx] = in[(size_t)r * Cc + cx];
    }
    __syncthreads();
    const int ox = blockIdx.y * 32 + tx;
#pragma unroll
    for (int i = 0; i < 4; i++) {
        int oy = blockIdx.x * 32 + ty + i * 8;
        float v = t[tx][ty + i * 8];
        float h = rna_tf32(v);
        float l = rna_tf32(v - h);
        float* row = out + (size_t)oy * (3 * R) + ox;
        row[0]     = h;
        row[R]     = l;
        row[2 * R] = h;
    }
}

// ---------------------------------------------------------------------------
// transpose + rna: V[R,Cc] -> VT[Cc,R]
// ---------------------------------------------------------------------------
__global__ void __launch_bounds__(256)
transpose_rna(const float* __restrict__ in, float* __restrict__ out, int R, int Cc)
{
    __shared__ float t[32][33];
    const int tx = threadIdx.x, ty = threadIdx.y;
    const int cx = blockIdx.x * 32 + tx;
#pragma unroll
    for (int i = 0; i < 4; i++) {
        int r = blockIdx.y * 32 + ty + i * 8;
        t[ty + i * 8][tx] = rna_tf32(in[(size_t)r * Cc + cx]);
    }
    __syncthreads();
    const int ox = blockIdx.y * 32 + tx;
#pragma unroll
    for (int i = 0; i < 4; i++) {
        int oy = blockIdx.x * 32 + ty + i * 8;
        out[(size_t)oy * R + ox] = t[tx][ty + i * 8];
    }
}

// ---------------------------------------------------------------------------
// row softmax, in place; probs rna-rounded (exact tf32 operands for PV GEMM)
// ---------------------------------------------------------------------------
__global__ void __launch_bounds__(256)
softmax_kernel(float* __restrict__ S)
{
    __shared__ float red[256];
    const int tid = threadIdx.x;
    float* p = S + (size_t)blockIdx.x * SEQ;

    float m = -INFINITY;
    for (int c = tid * 4; c < SEQ; c += 1024) {
        const float4 v = *(const float4*)(p + c);
        m = fmaxf(m, fmaxf(fmaxf(v.x, v.y), fmaxf(v.z, v.w)));
    }
    red[tid] = m; __syncthreads();
    for (int s = 128; s > 0; s >>= 1) { if (tid < s) red[tid] = fmaxf(red[tid], red[tid + s]); __syncthreads(); }
    m = red[0]; __syncthreads();

    float sum = 0.0f;
    for (int c = tid * 4; c < SEQ; c += 1024) {
        float4 v = *(const float4*)(p + c);
        v.x = expf(v.x - m); v.y = expf(v.y - m);
        v.z = expf(v.z - m); v.w = expf(v.w - m);
        *(float4*)(p + c) = v;
        sum += v.x + v.y + v.z + v.w;
    }
    red[tid] = sum; __syncthreads();
    for (int s = 128; s > 0; s >>= 1) { if (tid < s) red[tid] += red[tid + s]; __syncthreads(); }
    const float inv = 1.0f / red[0];
    __syncthreads();

    for (int c = tid * 4; c < SEQ; c += 1024) {
        float4 v = *(const float4*)(p + c);
        v.x = rna_tf32(v.x * inv); v.y = rna_tf32(v.y * inv);
        v.z = rna_tf32(v.z * inv); v.w = rna_tf32(v.w * inv);
        *(float4*)(p + c) = v;
    }
}

// ---------------------------------------------------------------------------
extern "C" void kernel_launch(void* const* d_in, const int* in_sizes, int n_in,
                              void* d_out, int out_size)
{
    const float* input = (const float*)d_in[0];
    const float* Wq    = (const float*)d_in[1];
    const float* Wk    = (const float*)d_in[2];
    const float* Wv    = (const float*)d_in[3];
    float*       out   = (float*)d_out;

    float *inCat, *WqCT, *WkCT, *WvCT, *QCat, *KCat, *V, *VT, *S;
    cudaGetSymbolAddress((void**)&inCat, g_inCat);
    cudaGetSymbolAddress((void**)&WqCT,  g_WqCT);
    cudaGetSymbolAddress((void**)&WkCT,  g_WkCT);
    cudaGetSymbolAddress((void**)&WvCT,  g_WvCT);
    cudaGetSymbolAddress((void**)&QCat,  g_QCat);
    cudaGetSymbolAddress((void**)&KCat,  g_KCat);
    cudaGetSymbolAddress((void**)&V,     g_V);
    cudaGetSymbolAddress((void**)&VT,    g_VT);
    cudaGetSymbolAddress((void**)&S,     g_S);

    const int smem_sz = NSTAGE * STAGE_BYTES;   // 73728
    cudaFuncSetAttribute(tf32_gemm, cudaFuncAttributeMaxDynamicSharedMemorySize, smem_sz);

    const float scale = 1.0f / 32.0f;   // 1/sqrt(1024)
    dim3 tb(32, 8);
    dim3 gProj(DOUT / 128, SEQ / 128);
    dim3 gS(SEQ / 128, SEQ / 128);

    // staging first (puts a projection GEMM into the profiled launch slot)
    transpose_split_cat<<<dim3(DOUT / 32, DIN / 32), tb>>>(Wq, WqCT, DIN, DOUT);
    split_cat<<<(SEQ * DIN / 4 + 255) / 256, 256>>>(input, inCat, SEQ, DIN);

    // Q projection, 3xTF32 (K=3072), epilogue writes QCat = [hi|hi|lo]
    tf32_gemm<<<gProj, 128, smem_sz>>>(inCat, WqCT, QCat, DOUT, 3 * DIN,
                                       3 * DIN, 3 * DIN, 1.0f, 1);

    transpose_split_cat<<<dim3(DOUT / 32, DIN / 32), tb>>>(Wk, WkCT, DIN, DOUT);
    // K projection, 3xTF32, epilogue writes KCat = [hi|lo|hi]
    tf32_gemm<<<gProj, 128, smem_sz>>>(inCat, WkCT, KCat, DOUT, 3 * DIN,
                                       3 * DIN, 3 * DIN, 1.0f, 2);

    transpose_split_cat<<<dim3(DOUT / 32, DIN / 32), tb>>>(Wv, WvCT, DIN, DOUT);
    // V projection, SINGLE-pass tf32 (hi blocks only via strides), plain out
    tf32_gemm<<<gProj, 128, smem_sz>>>(inCat, WvCT, V, DOUT, DIN,
                                       3 * DIN, 3 * DIN, 1.0f, 0);
    // V^T (rna) — PV operand
    transpose_rna<<<dim3(DOUT / 32, SEQ / 32), tb>>>(V, VT, SEQ, DOUT);

    // scores: S = (QCat @ KCat^T) * scale, 3xTF32 (K=3072)
    tf32_gemm<<<gS, 128, smem_sz>>>(QCat, KCat, S, SEQ, 3 * DOUT,
                                    3 * DOUT, 3 * DOUT, scale, 0);

    softmax_kernel<<<SEQ, 256>>>(S);

    // out = P @ (V^T)^T, single tf32
    tf32_gemm<<<gProj, 128, smem_sz>>>(S, VT, out, DOUT, SEQ,
                                       SEQ, SEQ, 1.0f, 0);
}

// round 7
// speedup vs baseline: 2.3600x; 1.3484x over previous
#include <cuda_runtime.h>
#include <cuda_fp16.h>
#include <math.h>
#include <stdint.h>

#define SEQ  4096
#define DIN  1024
#define DOUT 1024

// ---------------- scratch (__device__ globals, alloc-free rule) ----------------
__device__ __half g_inCatH[(size_t)SEQ * (3 * DIN)];    // [hi | hi | lo] of input
__device__ __half g_WqCTH[(size_t)DOUT * (3 * DIN)];    // [hi | lo | hi] of Wq^T
__device__ __half g_WkCTH[(size_t)DOUT * (3 * DIN)];
__device__ __half g_WvCTH[(size_t)DOUT * (3 * DIN)];
__device__ __half g_QCatH[(size_t)SEQ * (3 * DOUT)];    // [Qhi | Qhi | Qlo]
__device__ __half g_KCatH[(size_t)SEQ * (3 * DOUT)];    // [Khi | Klo | Khi]
__device__ float  g_V[(size_t)SEQ * DOUT];
__device__ float  g_VT[(size_t)DOUT * SEQ];             // rna(V^T)
__device__ float  g_S[(size_t)SEQ * SEQ];               // scores / probs

// ---------------- helpers ----------------
__device__ __forceinline__ float rna_tf32(float x) {
    float y;
    asm("cvt.rna.tf32.f32 %0, %1;" : "=f"(y) : "f"(x));
    return y;
}
#define CP_ASYNC16(saddr, gaddr) \
    asm volatile("cp.async.cg.shared.global [%0], [%1], 16;" :: "r"(saddr), "l"(gaddr))
#define CP_COMMIT() asm volatile("cp.async.commit_group;" ::: "memory")
#define CP_WAIT1()  asm volatile("cp.async.wait_group 1;" ::: "memory")

__device__ __forceinline__ uint32_t smem_u32(const void* p) {
    uint32_t a;
    asm("{ .reg .u64 t; cvta.to.shared.u64 t, %1; cvt.u32.u64 %0, t; }" : "=r"(a) : "l"(p));
    return a;
}

// fp16 m16n8k16 mma, fp32 accum (family-common)
__device__ __forceinline__ void mma_f16(float* d,
                                        uint32_t a0, uint32_t a1, uint32_t a2, uint32_t a3,
                                        uint32_t b0, uint32_t b1) {
    asm volatile("mma.sync.aligned.m16n8k16.row.col.f32.f16.f16.f32 "
                 "{%0,%1,%2,%3}, {%4,%5,%6,%7}, {%8,%9}, {%0,%1,%2,%3};"
                 : "+f"(d[0]), "+f"(d[1]), "+f"(d[2]), "+f"(d[3])
                 : "r"(a0), "r"(a1), "r"(a2), "r"(a3), "r"(b0), "r"(b1));
}
// tf32 m16n8k8 mma (PV path)
__device__ __forceinline__ void mma_tf32(float* d,
                                         uint32_t a0, uint32_t a1, uint32_t a2, uint32_t a3,
                                         uint32_t b0, uint32_t b1) {
    asm volatile("mma.sync.aligned.m16n8k8.row.col.f32.tf32.tf32.f32 "
                 "{%0,%1,%2,%3}, {%4,%5,%6,%7}, {%8,%9}, {%0,%1,%2,%3};"
                 : "+f"(d[0]), "+f"(d[1]), "+f"(d[2]), "+f"(d[3])
                 : "r"(a0), "r"(a1), "r"(a2), "r"(a3), "r"(b0), "r"(b1));
}

// ---------------------------------------------------------------------------
// fp16 GEMM: C = alpha * A[M,K] @ B[N,K]^T (half, K-major, strided)
// CTA 128x128x32, 4 warps (2Mx2N), warp 64x64 (4m x 8n m16n8k16).
// Smem stride 40 halfs (conflict-free frag loads), 2-stage cp.async.
// outMode: 0 plain f32, 1 split-cat A [hi|hi|lo] (half C), 2 split-cat B [hi|lo|hi]
// ---------------------------------------------------------------------------
#define PADH 40
#define OPH_HALFS (128 * PADH)            // halfs per operand tile
#define OPH_BYTES (OPH_HALFS * 2)         // 10240
#define STAGEH_BYTES (2 * OPH_BYTES)      // 20480

__global__ void __launch_bounds__(128, 2)
h16_gemm(const __half* __restrict__ A, const __half* __restrict__ B,
         void* __restrict__ Cv, int Ntot, int Kd, int lda, int ldb,
         float alpha, int outMode)
{
    extern __shared__ __half smh[];
    const uint32_t sbase = smem_u32(smh);

    // 8-row supertile raster swizzle for L2 reuse
    const int gx = gridDim.x, gy = gridDim.y;
    const int lin = blockIdx.y * gx + blockIdx.x;
    const int GROUP = 8;
    const int per = GROUP * gx;
    const int g = lin / per;
    const int rem = lin - g * per;
    const int rowsLeft = gy - g * GROUP;
    const int rows = (GROUP < rowsLeft) ? GROUP : rowsLeft;
    const int byi = g * GROUP + rem % rows;
    const int bxi = rem / rows;

    const int tid  = threadIdx.x;
    const int wid  = tid >> 5;
    const int lane = tid & 31;
    const int warpM = wid >> 1;
    const int warpN = wid & 1;
    const int gID  = lane >> 2;
    const int tig  = lane & 3;
    const int rowBase = byi * 128;
    const int colBase = bxi * 128;

    const int ldRow0 = tid >> 2;          // 0..31 (advances +32 per i)
    const int ldSeg  = tid & 3;           // 0..3 (8-half segments)

    auto load_stage = [&](int st, int k0) {
        const uint32_t sA = sbase + st * STAGEH_BYTES;
        const uint32_t sB = sA + OPH_BYTES;
#pragma unroll
        for (int i = 0; i < 4; i++) {
            const int row = ldRow0 + i * 32;
            CP_ASYNC16(sA + (row * PADH + ldSeg * 8) * 2,
                       A + (size_t)(rowBase + row) * lda + k0 + ldSeg * 8);
        }
#pragma unroll
        for (int i = 0; i < 4; i++) {
            const int row = ldRow0 + i * 32;
            CP_ASYNC16(sB + (row * PADH + ldSeg * 8) * 2,
                       B + (size_t)(colBase + row) * ldb + k0 + ldSeg * 8);
        }
    };

    float acc[4][8][4];
#pragma unroll
    for (int i = 0; i < 4; i++)
#pragma unroll
        for (int j = 0; j < 8; j++)
#pragma unroll
            for (int r = 0; r < 4; r++) acc[i][j][r] = 0.0f;

    const int NITER = Kd >> 5;

    load_stage(0, 0);
    CP_COMMIT();
    load_stage(1, 32);
    CP_COMMIT();

    for (int j = 0; j < NITER; j++) {
        CP_WAIT1();
        __syncthreads();

        const __half* fA = smh + ((j & 1) * STAGEH_BYTES) / 2;
        const __half* fB = fA + OPH_HALFS;

#pragma unroll
        for (int s = 0; s < 2; s++) {           // two k16 steps per BK=32
            const int c0 = s * 16 + 2 * tig;
            uint32_t af[4][4];
#pragma unroll
            for (int i = 0; i < 4; i++) {
                const int r0 = warpM * 64 + i * 16 + gID;
                af[i][0] = *(const uint32_t*)(fA + r0 * PADH + c0);
                af[i][1] = *(const uint32_t*)(fA + (r0 + 8) * PADH + c0);
                af[i][2] = *(const uint32_t*)(fA + r0 * PADH + c0 + 8);
                af[i][3] = *(const uint32_t*)(fA + (r0 + 8) * PADH + c0 + 8);
            }
            uint32_t bf[8][2];
#pragma unroll
            for (int jn = 0; jn < 8; jn++) {
                const int n0 = warpN * 64 + jn * 8 + gID;
                bf[jn][0] = *(const uint32_t*)(fB + n0 * PADH + c0);
                bf[jn][1] = *(const uint32_t*)(fB + n0 * PADH + c0 + 8);
            }
#pragma unroll
            for (int i = 0; i < 4; i++)
#pragma unroll
                for (int jn = 0; jn < 8; jn++)
                    mma_f16(acc[i][jn], af[i][0], af[i][1], af[i][2], af[i][3],
                            bf[jn][0], bf[jn][1]);
        }
        __syncthreads();
        if (j + 2 < NITER) load_stage((j + 2) & 1, (j + 2) * 32);
        CP_COMMIT();
    }

    // ---- epilogue ----
#pragma unroll
    for (int i = 0; i < 4; i++) {
        const int r0 = rowBase + warpM * 64 + i * 16 + gID;
#pragma unroll
        for (int jn = 0; jn < 8; jn++) {
            const int c = colBase + warpN * 64 + jn * 8 + tig * 2;
#pragma unroll
            for (int half = 0; half < 2; half++) {
                const int r = r0 + half * 8;
                float2 v;
                v.x = alpha * acc[i][jn][half * 2 + 0];
                v.y = alpha * acc[i][jn][half * 2 + 1];
                if (outMode == 0) {
                    *(float2*)((float*)Cv + (size_t)r * Ntot + c) = v;
                } else {
                    __half2 h = __floats2half2_rn(v.x, v.y);
                    float2 hf = __half22float2(h);
                    __half2 l = __floats2half2_rn(v.x - hf.x, v.y - hf.y);
                    __half* row = (__half*)Cv + (size_t)r * (3 * Ntot) + c;
                    if (outMode == 1) {          // A-split: [hi | hi | lo]
                        *(__half2*)(row)            = h;
                        *(__half2*)(row + Ntot)     = h;
                        *(__half2*)(row + 2 * Ntot) = l;
                    } else {                     // B-split: [hi | lo | hi]
                        *(__half2*)(row)            = h;
                        *(__half2*)(row + Ntot)     = l;
                        *(__half2*)(row + 2 * Ntot) = h;
                    }
                }
            }
        }
    }
}

// ---------------------------------------------------------------------------
// tf32 GEMM for the PV product (fp32 in/out), as validated in R4/R5.
// ---------------------------------------------------------------------------
#define PAD_STRIDE 36
#define OP_BYTES   (128 * PAD_STRIDE * 4)
#define STAGE_BYTES (2 * OP_BYTES)

__global__ void __launch_bounds__(128, 2)
tf32_gemm(const float* __restrict__ A, const float* __restrict__ B,
          float* __restrict__ C, int Ntot, int Kd, int lda, int ldb, float alpha)
{
    extern __shared__ float smf[];
    const uint32_t sbase = smem_u32(smf);

    const int gx = gridDim.x, gy = gridDim.y;
    const int lin = blockIdx.y * gx + blockIdx.x;
    const int GROUP = 8;
    const int per = GROUP * gx;
    const int g = lin / per;
    const int rem = lin - g * per;
    const int rowsLeft = gy - g * GROUP;
    const int rows = (GROUP < rowsLeft) ? GROUP : rowsLeft;
    const int byi = g * GROUP + rem % rows;
    const int bxi = rem / rows;

    const int tid  = threadIdx.x;
    const int wid  = tid >> 5;
    const int lane = tid & 31;
    const int warpM = wid >> 1;
    const int warpN = wid & 1;
    const int gID  = lane >> 2;
    const int tig  = lane & 3;
    const int rowBase = byi * 128;
    const int colBase = bxi * 128;

    const int ldRow0 = tid >> 3;
    const int ldSeg  = tid & 7;

    auto load_stage = [&](int st, int k0) {
        const uint32_t sA = sbase + st * STAGE_BYTES;
        const uint32_t sB = sA + OP_BYTES;
#pragma unroll
        for (int i = 0; i < 8; i++) {
            const int row = ldRow0 + i * 16;
            CP_ASYNC16(sA + (row * PAD_STRIDE + ldSeg * 4) * 4,
                       A + (size_t)(rowBase + row) * lda + k0 + ldSeg * 4);
        }
#pragma unroll
        for (int i = 0; i < 8; i++) {
            const int row = ldRow0 + i * 16;
            CP_ASYNC16(sB + (row * PAD_STRIDE + ldSeg * 4) * 4,
                       B + (size_t)(colBase + row) * ldb + k0 + ldSeg * 4);
        }
    };

    float acc[4][8][4];
#pragma unroll
    for (int i = 0; i < 4; i++)
#pragma unroll
        for (int j = 0; j < 8; j++)
#pragma unroll
            for (int r = 0; r < 4; r++) acc[i][j][r] = 0.0f;

    const int NITER = Kd >> 5;

    load_stage(0, 0);
    CP_COMMIT();
    load_stage(1, 32);
    CP_COMMIT();

    for (int j = 0; j < NITER; j++) {
        CP_WAIT1();
        __syncthreads();

        const float* fA = (const float*)(smf) + ((j & 1) * STAGE_BYTES) / 4;
        const float* fB = fA + OP_BYTES / 4;

#pragma unroll
        for (int s = 0; s < 4; s++) {
            uint32_t af[4][4];
#pragma unroll
            for (int i = 0; i < 4; i++) {
                const int r0 = warpM * 64 + i * 16 + gID;
                const int c0 = s * 8 + tig;
                af[i][0] = __float_as_uint(fA[r0 * PAD_STRIDE + c0]);
                af[i][1] = __float_as_uint(fA[(r0 + 8) * PAD_STRIDE + c0]);
                af[i][2] = __float_as_uint(fA[r0 * PAD_STRIDE + c0 + 4]);
                af[i][3] = __float_as_uint(fA[(r0 + 8) * PAD_STRIDE + c0 + 4]);
            }
            uint32_t bf[8][2];
#pragma unroll
            for (int jn = 0; jn < 8; jn++) {
                const int n0 = warpN * 64 + jn * 8 + gID;
                const int c0 = s * 8 + tig;
                bf[jn][0] = __float_as_uint(fB[n0 * PAD_STRIDE + c0]);
                bf[jn][1] = __float_as_uint(fB[n0 * PAD_STRIDE + c0 + 4]);
            }
#pragma unroll
            for (int i = 0; i < 4; i++)
#pragma unroll
                for (int jn = 0; jn < 8; jn++)
                    mma_tf32(acc[i][jn], af[i][0], af[i][1], af[i][2], af[i][3],
                             bf[jn][0], bf[jn][1]);
        }
        __syncthreads();
        if (j + 2 < NITER) load_stage((j + 2) & 1, (j + 2) * 32);
        CP_COMMIT();
    }

#pragma unroll
    for (int i = 0; i < 4; i++) {
        const int r0 = rowBase + warpM * 64 + i * 16 + gID;
#pragma unroll
        for (int jn = 0; jn < 8; jn++) {
            const int c = colBase + warpN * 64 + jn * 8 + tig * 2;
#pragma unroll
            for (int half = 0; half < 2; half++) {
                const int r = r0 + half * 8;
                float2 v;
                v.x = alpha * acc[i][jn][half * 2 + 0];
                v.y = alpha * acc[i][jn][half * 2 + 1];
                *(float2*)(C + (size_t)r * Ntot + c) = v;
            }
        }
    }
}

// ---------------------------------------------------------------------------
// split-cat to half: in[R,C] f32 -> out[R,3C] half, A mode [hi|hi|lo]
// ---------------------------------------------------------------------------
__global__ void __launch_bounds__(256)
split_cat_h(const float* __restrict__ in, __half* __restrict__ out, int R, int C)
{
    int i = blockIdx.x * 256 + threadIdx.x;
    int n4 = R * C / 4;
    if (i >= n4) return;
    float4 v = ((const float4*)in)[i];
    __half2 h0 = __floats2half2_rn(v.x, v.y);
    __half2 h1 = __floats2half2_rn(v.z, v.w);
    float2 f0 = __half22float2(h0), f1 = __half22float2(h1);
    __half2 l0 = __floats2half2_rn(v.x - f0.x, v.y - f0.y);
    __half2 l1 = __floats2half2_rn(v.z - f1.x, v.w - f1.y);
    int e = i * 4;
    int r = e / C, c = e % C;
    __half* row = out + (size_t)r * (3 * C) + c;
    *(__half2*)(row)             = h0; *(__half2*)(row + 2)         = h1;
    *(__half2*)(row + C)         = h0; *(__half2*)(row + C + 2)     = h1;
    *(__half2*)(row + 2 * C)     = l0; *(__half2*)(row + 2 * C + 2) = l1;
}

// ---------------------------------------------------------------------------
// transpose + split-cat half (B mode): W[R,Cc] -> out[Cc,3R] = [hi|lo|hi] of W^T
// ---------------------------------------------------------------------------
__global__ void __launch_bounds__(256)
transpose_split_cat_h(const float* __restrict__ in, __half* __restrict__ out, int R, int Cc)
{
    __shared__ float t[32][33];
    const int tx = threadIdx.x, ty = threadIdx.y;
    const int cx = blockIdx.x * 32 + tx;
#pragma unroll
    for (int i = 0; i < 4; i++) {
        int r = blockIdx.y * 32 + ty + i * 8;
        t[ty + i * 8][tx] = in[(size_t)r * Cc + cx];
    }
    __syncthreads();
    const int ox = blockIdx.y * 32 + tx;
#pragma unroll
    for (int i = 0; i < 4; i++) {
        int oy = blockIdx.x * 32 + ty + i * 8;
        float v = t[tx][ty + i * 8];
        __half h = __float2half_rn(v);
        __half l = __float2half_rn(v - __half2float(h));
        __half* row = out + (size_t)oy * (3 * R) + ox;
        row[0]     = h;
        row[R]     = l;
        row[2 * R] = h;
    }
}

// ---------------------------------------------------------------------------
// transpose + rna: V[R,Cc] f32 -> VT[Cc,R] f32 (PV tf32 operand)
// ---------------------------------------------------------------------------
__global__ void __launch_bounds__(256)
transpose_rna(const float* __restrict__ in, float* __restrict__ out, int R, int Cc)
{
    __shared__ float t[32][33];
    const int tx = threadIdx.x, ty = threadIdx.y;
    const int cx = blockIdx.x * 32 + tx;
#pragma unroll
    for (int i = 0; i < 4; i++) {
        int r = blockIdx.y * 32 + ty + i * 8;
        t[ty + i * 8][tx] = rna_tf32(in[(size_t)r * Cc + cx]);
    }
    __syncthreads();
    const int ox = blockIdx.y * 32 + tx;
#pragma unroll
    for (int i = 0; i < 4; i++) {
        int oy = blockIdx.x * 32 + ty + i * 8;
        out[(size_t)oy * R + ox] = t[tx][ty + i * 8];
    }
}

// ---------------------------------------------------------------------------
// row softmax, in place; probs rna-rounded (exact tf32 operands for PV GEMM)
// ---------------------------------------------------------------------------
__global__ void __launch_bounds__(256)
softmax_kernel(float* __restrict__ S)
{
    __shared__ float red[256];
    const int tid = threadIdx.x;
    float* p = S + (size_t)blockIdx.x * SEQ;

    float m = -INFINITY;
    for (int c = tid * 4; c < SEQ; c += 1024) {
        const float4 v = *(const float4*)(p + c);
        m = fmaxf(m, fmaxf(fmaxf(v.x, v.y), fmaxf(v.z, v.w)));
    }
    red[tid] = m; __syncthreads();
    for (int s = 128; s > 0; s >>= 1) { if (tid < s) red[tid] = fmaxf(red[tid], red[tid + s]); __syncthreads(); }
    m = red[0]; __syncthreads();

    float sum = 0.0f;
    for (int c = tid * 4; c < SEQ; c += 1024) {
        float4 v = *(const float4*)(p + c);
        v.x = expf(v.x - m); v.y = expf(v.y - m);
        v.z = expf(v.z - m); v.w = expf(v.w - m);
        *(float4*)(p + c) = v;
        sum += v.x + v.y + v.z + v.w;
    }
    red[tid] = sum; __syncthreads();
    for (int s = 128; s > 0; s >>= 1) { if (tid < s) red[tid] += red[tid + s]; __syncthreads(); }
    const float inv = 1.0f / red[0];
    __syncthreads();

    for (int c = tid * 4; c < SEQ; c += 1024) {
        float4 v = *(const float4*)(p + c);
        v.x = rna_tf32(v.x * inv); v.y = rna_tf32(v.y * inv);
        v.z = rna_tf32(v.z * inv); v.w = rna_tf32(v.w * inv);
        *(float4*)(p + c) = v;
    }
}

// ---------------------------------------------------------------------------
extern "C" void kernel_launch(void* const* d_in, const int* in_sizes, int n_in,
                              void* d_out, int out_size)
{
    const float* input = (const float*)d_in[0];
    const float* Wq    = (const float*)d_in[1];
    const float* Wk    = (const float*)d_in[2];
    const float* Wv    = (const float*)d_in[3];
    float*       out   = (float*)d_out;

    __half *inCatH, *WqCTH, *WkCTH, *WvCTH, *QCatH, *KCatH;
    float *V, *VT, *S;
    cudaGetSymbolAddress((void**)&inCatH, g_inCatH);
    cudaGetSymbolAddress((void**)&WqCTH,  g_WqCTH);
    cudaGetSymbolAddress((void**)&WkCTH,  g_WkCTH);
    cudaGetSymbolAddress((void**)&WvCTH,  g_WvCTH);
    cudaGetSymbolAddress((void**)&QCatH,  g_QCatH);
    cudaGetSymbolAddress((void**)&KCatH,  g_KCatH);
    cudaGetSymbolAddress((void**)&V,      g_V);
    cudaGetSymbolAddress((void**)&VT,     g_VT);
    cudaGetSymbolAddress((void**)&S,      g_S);

    cudaFuncSetAttribute(h16_gemm, cudaFuncAttributeMaxDynamicSharedMemorySize,
                         2 * STAGEH_BYTES);
    cudaFuncSetAttribute(tf32_gemm, cudaFuncAttributeMaxDynamicSharedMemorySize,
                         2 * STAGE_BYTES);

    const float scale = 1.0f / 32.0f;   // 1/sqrt(1024)
    dim3 tb(32, 8);
    dim3 gProj(DOUT / 128, SEQ / 128);
    dim3 gS(SEQ / 128, SEQ / 128);
    const int smemH = 2 * STAGEH_BYTES;
    const int smemT = 2 * STAGE_BYTES;

    // staging (launches 1-4)
    split_cat_h<<<(SEQ * DIN / 4 + 255) / 256, 256>>>(input, inCatH, SEQ, DIN);
    transpose_split_cat_h<<<dim3(DOUT / 32, DIN / 32), tb>>>(Wq, WqCTH, DIN, DOUT);
    transpose_split_cat_h<<<dim3(DOUT / 32, DIN / 32), tb>>>(Wk, WkCTH, DIN, DOUT);
    transpose_split_cat_h<<<dim3(DOUT / 32, DIN / 32), tb>>>(Wv, WvCTH, DIN, DOUT);

    // Q projection (launch 5), fp16 3-pass, epilogue writes QCatH = [hi|hi|lo]
    h16_gemm<<<gProj, 128, smemH>>>(inCatH, WqCTH, QCatH, DOUT, 3 * DIN,
                                    3 * DIN, 3 * DIN, 1.0f, 1);
    // K projection (launch 6 — profiled), epilogue writes KCatH = [hi|lo|hi]
    h16_gemm<<<gProj, 128, smemH>>>(inCatH, WkCTH, KCatH, DOUT, 3 * DIN,
                                    3 * DIN, 3 * DIN, 1.0f, 2);
    // V projection, fp16 3-pass (fp32-accurate V), plain f32 out
    h16_gemm<<<gProj, 128, smemH>>>(inCatH, WvCTH, V, DOUT, 3 * DIN,
                                    3 * DIN, 3 * DIN, 1.0f, 0);
    // V^T (rna) — PV operand
    transpose_rna<<<dim3(DOUT / 32, SEQ / 32), tb>>>(V, VT, SEQ, DOUT);

    // scores: S = (QCat @ KCat^T) * scale, fp16 3-pass (K = 3072)
    h16_gemm<<<gS, 128, smemH>>>(QCatH, KCatH, S, SEQ, 3 * DOUT,
                                 3 * DOUT, 3 * DOUT, scale, 0);

    softmax_kernel<<<SEQ, 256>>>(S);

    // out = P @ (V^T)^T, single tf32 pass
    tf32_gemm<<<gProj, 128, smemT>>>(S, VT, out, DOUT, SEQ, SEQ, SEQ, 1.0f);
}

// round 8
// speedup vs baseline: 2.6878x; 1.1389x over previous
#include <cuda_runtime.h>
#include <cuda_fp16.h>
#include <math.h>
#include <stdint.h>

#define SEQ  4096
#define DIN  1024
#define DOUT 1024

// ---------------- scratch (__device__ globals, alloc-free rule) ----------------
__device__ __half g_inCatH[(size_t)SEQ * (3 * DIN)];    // [hi | hi | lo] of input
__device__ __half g_WqCTH[(size_t)DOUT * (3 * DIN)];    // [hi | lo | hi] of Wq^T
__device__ __half g_WkCTH[(size_t)DOUT * (3 * DIN)];
__device__ __half g_WvCTH[(size_t)DOUT * (3 * DIN)];
__device__ __half g_QCatH[(size_t)SEQ * (3 * DOUT)];    // [Qhi | Qhi | Qlo]
__device__ __half g_KCatH[(size_t)SEQ * (3 * DOUT)];    // [Khi | Klo | Khi]
__device__ float  g_V[(size_t)SEQ * DOUT];
__device__ float  g_VT[(size_t)DOUT * SEQ];             // rna(V^T)
__device__ float  g_S[(size_t)SEQ * SEQ];               // scores / unnorm probs
__device__ float  g_invS[SEQ];                          // 1/rowsum

// ---------------- helpers ----------------
__device__ __forceinline__ float rna_tf32(float x) {
    float y;
    asm("cvt.rna.tf32.f32 %0, %1;" : "=f"(y) : "f"(x));
    return y;
}
#define CP_ASYNC16(saddr, gaddr) \
    asm volatile("cp.async.cg.shared.global [%0], [%1], 16;" :: "r"(saddr), "l"(gaddr))
#define CP_COMMIT() asm volatile("cp.async.commit_group;" ::: "memory")
#define CP_WAIT_GROUP(n) asm volatile("cp.async.wait_group " #n ";" ::: "memory")

__device__ __forceinline__ uint32_t smem_u32(const void* p) {
    uint32_t a;
    asm("{ .reg .u64 t; cvta.to.shared.u64 t, %1; cvt.u32.u64 %0, t; }" : "=r"(a) : "l"(p));
    return a;
}
#define LDSM_X4(r0, r1, r2, r3, addr) \
    asm volatile("ldmatrix.sync.aligned.m8n8.x4.shared.b16 {%0,%1,%2,%3}, [%4];" \
                 : "=r"(r0), "=r"(r1), "=r"(r2), "=r"(r3) : "r"(addr))

// fp16 m16n8k16 mma, fp32 accum (family-common)
__device__ __forceinline__ void mma_f16(float* d,
                                        uint32_t a0, uint32_t a1, uint32_t a2, uint32_t a3,
                                        uint32_t b0, uint32_t b1) {
    asm volatile("mma.sync.aligned.m16n8k16.row.col.f32.f16.f16.f32 "
                 "{%0,%1,%2,%3}, {%4,%5,%6,%7}, {%8,%9}, {%0,%1,%2,%3};"
                 : "+f"(d[0]), "+f"(d[1]), "+f"(d[2]), "+f"(d[3])
                 : "r"(a0), "r"(a1), "r"(a2), "r"(a3), "r"(b0), "r"(b1));
}
// tf32 m16n8k8 mma (PV path)
__device__ __forceinline__ void mma_tf32(float* d,
                                         uint32_t a0, uint32_t a1, uint32_t a2, uint32_t a3,
                                         uint32_t b0, uint32_t b1) {
    asm volatile("mma.sync.aligned.m16n8k8.row.col.f32.tf32.tf32.f32 "
                 "{%0,%1,%2,%3}, {%4,%5,%6,%7}, {%8,%9}, {%0,%1,%2,%3};"
                 : "+f"(d[0]), "+f"(d[1]), "+f"(d[2]), "+f"(d[3])
                 : "r"(a0), "r"(a1), "r"(a2), "r"(a3), "r"(b0), "r"(b1));
}

// ---------------------------------------------------------------------------
// fp16 GEMM: C = alpha * A[M,K] @ B[N,K]^T (half, K-major, strided)
// CTA 128x128x32, 4 warps (2Mx2N), warp 64x64 (4m x 8n m16n8k16), ldmatrix.
// 4-stage cp.async pipeline, ONE syncthreads per k-iter.
// outMode: 0 plain f32, 1 split-cat A [hi|hi|lo] (half C), 2 split-cat B [hi|lo|hi]
// ---------------------------------------------------------------------------
#define PADH 40
#define OPH_HALFS (128 * PADH)
#define OPH_BYTES (OPH_HALFS * 2)         // 10240
#define STAGEH_BYTES (2 * OPH_BYTES)      // 20480
#define NSTAGE_H 4

__global__ void __launch_bounds__(128, 2)
h16_gemm(const __half* __restrict__ A, const __half* __restrict__ B,
         void* __restrict__ Cv, int Ntot, int Kd, int lda, int ldb,
         float alpha, int outMode)
{
    extern __shared__ __half smh[];
    const uint32_t sbase = smem_u32(smh);

    // 8-row supertile raster swizzle for L2 reuse
    const int gx = gridDim.x, gy = gridDim.y;
    const int lin = blockIdx.y * gx + blockIdx.x;
    const int GROUP = 8;
    const int per = GROUP * gx;
    const int g = lin / per;
    const int rem = lin - g * per;
    const int rowsLeft = gy - g * GROUP;
    const int rows = (GROUP < rowsLeft) ? GROUP : rowsLeft;
    const int byi = g * GROUP + rem % rows;
    const int bxi = rem / rows;

    const int tid  = threadIdx.x;
    const int wid  = tid >> 5;
    const int lane = tid & 31;
    const int warpM = wid >> 1;
    const int warpN = wid & 1;
    const int gID  = lane >> 2;
    const int tig  = lane & 3;
    const int rowBase = byi * 128;
    const int colBase = bxi * 128;

    // ldmatrix per-lane tile offsets (in halfs)
    const int lt = lane >> 3;             // 0..3 tile idx
    const int l7 = lane & 7;
    const int aOff = ((lt & 1) * 8 + l7) * PADH + (lt >> 1) * 8;
    const int bOff = ((lt >> 1) * 8 + l7) * PADH + (lt & 1) * 8;

    const int ldRow0 = tid >> 2;          // 0..31 (advances +32 per i)
    const int ldSeg  = tid & 3;           // 8-half segments

    auto load_stage = [&](int st, int k0) {
        const uint32_t sA = sbase + st * STAGEH_BYTES;
        const uint32_t sB = sA + OPH_BYTES;
#pragma unroll
        for (int i = 0; i < 4; i++) {
            const int row = ldRow0 + i * 32;
            CP_ASYNC16(sA + (row * PADH + ldSeg * 8) * 2,
                       A + (size_t)(rowBase + row) * lda + k0 + ldSeg * 8);
        }
#pragma unroll
        for (int i = 0; i < 4; i++) {
            const int row = ldRow0 + i * 32;
            CP_ASYNC16(sB + (row * PADH + ldSeg * 8) * 2,
                       B + (size_t)(colBase + row) * ldb + k0 + ldSeg * 8);
        }
    };

    float acc[4][8][4];
#pragma unroll
    for (int i = 0; i < 4; i++)
#pragma unroll
        for (int j = 0; j < 8; j++)
#pragma unroll
            for (int r = 0; r < 4; r++) acc[i][j][r] = 0.0f;

    const int NITER = Kd >> 5;

    // preload 3 stages
    load_stage(0, 0);  CP_COMMIT();
    load_stage(1, 32); CP_COMMIT();
    load_stage(2, 64); CP_COMMIT();

    for (int j = 0; j < NITER; j++) {
        CP_WAIT_GROUP(2);                 // stage j resident
        __syncthreads();                  // single barrier per iter
        if (j + 3 < NITER) load_stage((j + 3) & 3, (j + 3) * 32);
        CP_COMMIT();

        const uint32_t sA = sbase + (j & 3) * STAGEH_BYTES;
        const uint32_t sB = sA + OPH_BYTES;

#pragma unroll
        for (int s = 0; s < 2; s++) {
            uint32_t af[4][4];
#pragma unroll
            for (int i = 0; i < 4; i++) {
                const uint32_t addr = sA + (((warpM * 64 + i * 16) * PADH) + s * 16 + aOff) * 2;
                LDSM_X4(af[i][0], af[i][1], af[i][2], af[i][3], addr);
            }
            uint32_t bf[8][2];
#pragma unroll
            for (int p = 0; p < 4; p++) {
                const uint32_t addr = sB + (((warpN * 64 + p * 16) * PADH) + s * 16 + bOff) * 2;
                LDSM_X4(bf[2 * p][0], bf[2 * p][1], bf[2 * p + 1][0], bf[2 * p + 1][1], addr);
            }
#pragma unroll
            for (int i = 0; i < 4; i++)
#pragma unroll
                for (int jn = 0; jn < 8; jn++)
                    mma_f16(acc[i][jn], af[i][0], af[i][1], af[i][2], af[i][3],
                            bf[jn][0], bf[jn][1]);
        }
    }

    // ---- epilogue ----
#pragma unroll
    for (int i = 0; i < 4; i++) {
        const int r0 = rowBase + warpM * 64 + i * 16 + gID;
#pragma unroll
        for (int jn = 0; jn < 8; jn++) {
            const int c = colBase + warpN * 64 + jn * 8 + tig * 2;
#pragma unroll
            for (int half = 0; half < 2; half++) {
                const int r = r0 + half * 8;
                float2 v;
                v.x = alpha * acc[i][jn][half * 2 + 0];
                v.y = alpha * acc[i][jn][half * 2 + 1];
                if (outMode == 0) {
                    *(float2*)((float*)Cv + (size_t)r * Ntot + c) = v;
                } else {
                    __half2 h = __floats2half2_rn(v.x, v.y);
                    float2 hf = __half22float2(h);
                    __half2 l = __floats2half2_rn(v.x - hf.x, v.y - hf.y);
                    __half* row = (__half*)Cv + (size_t)r * (3 * Ntot) + c;
                    if (outMode == 1) {          // A-split: [hi | hi | lo]
                        *(__half2*)(row)            = h;
                        *(__half2*)(row + Ntot)     = h;
                        *(__half2*)(row + 2 * Ntot) = l;
                    } else {                     // B-split: [hi | lo | hi]
                        *(__half2*)(row)            = h;
                        *(__half2*)(row + Ntot)     = l;
                        *(__half2*)(row + 2 * Ntot) = h;
                    }
                }
            }
        }
    }
}

// ---------------------------------------------------------------------------
// tf32 GEMM (PV): C = rowScale[r] * A[M,K] @ B[N,K]^T   (validated R4-R7 body)
// ---------------------------------------------------------------------------
#define PAD_STRIDE 36
#define OP_BYTES   (128 * PAD_STRIDE * 4)
#define STAGE_BYTES (2 * OP_BYTES)

__global__ void __launch_bounds__(128, 2)
tf32_gemm(const float* __restrict__ A, const float* __restrict__ B,
          float* __restrict__ C, int Ntot, int Kd, int lda, int ldb,
          float alpha, const float* __restrict__ rowScale)
{
    extern __shared__ float smf[];
    const uint32_t sbase = smem_u32(smf);

    const int gx = gridDim.x, gy = gridDim.y;
    const int lin = blockIdx.y * gx + blockIdx.x;
    const int GROUP = 8;
    const int per = GROUP * gx;
    const int g = lin / per;
    const int rem = lin - g * per;
    const int rowsLeft = gy - g * GROUP;
    const int rows = (GROUP < rowsLeft) ? GROUP : rowsLeft;
    const int byi = g * GROUP + rem % rows;
    const int bxi = rem / rows;

    const int tid  = threadIdx.x;
    const int wid  = tid >> 5;
    const int lane = tid & 31;
    const int warpM = wid >> 1;
    const int warpN = wid & 1;
    const int gID  = lane >> 2;
    const int tig  = lane & 3;
    const int rowBase = byi * 128;
    const int colBase = bxi * 128;

    const int ldRow0 = tid >> 3;
    const int ldSeg  = tid & 7;

    auto load_stage = [&](int st, int k0) {
        const uint32_t sA = sbase + st * STAGE_BYTES;
        const uint32_t sB = sA + OP_BYTES;
#pragma unroll
        for (int i = 0; i < 8; i++) {
            const int row = ldRow0 + i * 16;
            CP_ASYNC16(sA + (row * PAD_STRIDE + ldSeg * 4) * 4,
                       A + (size_t)(rowBase + row) * lda + k0 + ldSeg * 4);
        }
#pragma unroll
        for (int i = 0; i < 8; i++) {
            const int row = ldRow0 + i * 16;
            CP_ASYNC16(sB + (row * PAD_STRIDE + ldSeg * 4) * 4,
                       B + (size_t)(colBase + row) * ldb + k0 + ldSeg * 4);
        }
    };

    float acc[4][8][4];
#pragma unroll
    for (int i = 0; i < 4; i++)
#pragma unroll
        for (int j = 0; j < 8; j++)
#pragma unroll
            for (int r = 0; r < 4; r++) acc[i][j][r] = 0.0f;

    const int NITER = Kd >> 5;

    load_stage(0, 0);
    CP_COMMIT();
    load_stage(1, 32);
    CP_COMMIT();

    for (int j = 0; j < NITER; j++) {
        CP_WAIT_GROUP(1);
        __syncthreads();

        const float* fA = (const float*)(smf) + ((j & 1) * STAGE_BYTES) / 4;
        const float* fB = fA + OP_BYTES / 4;

#pragma unroll
        for (int s = 0; s < 4; s++) {
            uint32_t af[4][4];
#pragma unroll
            for (int i = 0; i < 4; i++) {
                const int r0 = warpM * 64 + i * 16 + gID;
                const int c0 = s * 8 + tig;
                af[i][0] = __float_as_uint(fA[r0 * PAD_STRIDE + c0]);
                af[i][1] = __float_as_uint(fA[(r0 + 8) * PAD_STRIDE + c0]);
                af[i][2] = __float_as_uint(fA[r0 * PAD_STRIDE + c0 + 4]);
                af[i][3] = __float_as_uint(fA[(r0 + 8) * PAD_STRIDE + c0 + 4]);
            }
            uint32_t bf[8][2];
#pragma unroll
            for (int jn = 0; jn < 8; jn++) {
                const int n0 = warpN * 64 + jn * 8 + gID;
                const int c0 = s * 8 + tig;
                bf[jn][0] = __float_as_uint(fB[n0 * PAD_STRIDE + c0]);
                bf[jn][1] = __float_as_uint(fB[n0 * PAD_STRIDE + c0 + 4]);
            }
#pragma unroll
            for (int i = 0; i < 4; i++)
#pragma unroll
                for (int jn = 0; jn < 8; jn++)
                    mma_tf32(acc[i][jn], af[i][0], af[i][1], af[i][2], af[i][3],
                             bf[jn][0], bf[jn][1]);
        }
        __syncthreads();
        if (j + 2 < NITER) load_stage((j + 2) & 1, (j + 2) * 32);
        CP_COMMIT();
    }

#pragma unroll
    for (int i = 0; i < 4; i++) {
        const int r0 = rowBase + warpM * 64 + i * 16 + gID;
#pragma unroll
        for (int jn = 0; jn < 8; jn++) {
            const int c = colBase + warpN * 64 + jn * 8 + tig * 2;
#pragma unroll
            for (int half = 0; half < 2; half++) {
                const int r = r0 + half * 8;
                const float sc = rowScale ? (alpha * rowScale[r]) : alpha;
                float2 v;
                v.x = sc * acc[i][jn][half * 2 + 0];
                v.y = sc * acc[i][jn][half * 2 + 1];
                *(float2*)(C + (size_t)r * Ntot + c) = v;
            }
        }
    }
}

// ---------------------------------------------------------------------------
// split-cat to half: in[R,C] f32 -> out[R,3C] half, A mode [hi|hi|lo]
// ---------------------------------------------------------------------------
__global__ void __launch_bounds__(256)
split_cat_h(const float* __restrict__ in, __half* __restrict__ out, int R, int C)
{
    int i = blockIdx.x * 256 + threadIdx.x;
    int n4 = R * C / 4;
    if (i >= n4) return;
    float4 v = ((const float4*)in)[i];
    __half2 h0 = __floats2half2_rn(v.x, v.y);
    __half2 h1 = __floats2half2_rn(v.z, v.w);
    float2 f0 = __half22float2(h0), f1 = __half22float2(h1);
    __half2 l0 = __floats2half2_rn(v.x - f0.x, v.y - f0.y);
    __half2 l1 = __floats2half2_rn(v.z - f1.x, v.w - f1.y);
    int e = i * 4;
    int r = e / C, c = e % C;
    __half* row = out + (size_t)r * (3 * C) + c;
    *(__half2*)(row)             = h0; *(__half2*)(row + 2)         = h1;
    *(__half2*)(row + C)         = h0; *(__half2*)(row + C + 2)     = h1;
    *(__half2*)(row + 2 * C)     = l0; *(__half2*)(row + 2 * C + 2) = l1;
}

// ---------------------------------------------------------------------------
// batched transpose + split-cat half (B mode) for the 3 weight matrices
// ---------------------------------------------------------------------------
__global__ void __launch_bounds__(256)
transpose_split_cat_h3(const float* __restrict__ W0, const float* __restrict__ W1,
                       const float* __restrict__ W2,
                       __half* __restrict__ O0, __half* __restrict__ O1,
                       __half* __restrict__ O2, int R, int Cc)
{
    const float* in  = (blockIdx.z == 0) ? W0 : (blockIdx.z == 1) ? W1 : W2;
    __half*      out = (blockIdx.z == 0) ? O0 : (blockIdx.z == 1) ? O1 : O2;

    __shared__ float t[32][33];
    const int tx = threadIdx.x, ty = threadIdx.y;
    const int cx = blockIdx.x * 32 + tx;
#pragma unroll
    for (int i = 0; i < 4; i++) {
        int r = blockIdx.y * 32 + ty + i * 8;
        t[ty + i * 8][tx] = in[(size_t)r * Cc + cx];
    }
    __syncthreads();
    const int ox = blockIdx.y * 32 + tx;
#pragma unroll
    for (int i = 0; i < 4; i++) {
        int oy = blockIdx.x * 32 + ty + i * 8;
        float v = t[tx][ty + i * 8];
        __half h = __float2half_rn(v);
        __half l = __float2half_rn(v - __half2float(h));
        __half* row = out + (size_t)oy * (3 * R) + ox;
        row[0]     = h;
        row[R]     = l;
        row[2 * R] = h;
    }
}

// ---------------------------------------------------------------------------
// transpose + rna: V[R,Cc] f32 -> VT[Cc,R] f32 (PV tf32 operand)
// ---------------------------------------------------------------------------
__global__ void __launch_bounds__(256)
transpose_rna(const float* __restrict__ in, float* __restrict__ out, int R, int Cc)
{
    __shared__ float t[32][33];
    const int tx = threadIdx.x, ty = threadIdx.y;
    const int cx = blockIdx.x * 32 + tx;
#pragma unroll
    for (int i = 0; i < 4; i++) {
        int r = blockIdx.y * 32 + ty + i * 8;
        t[ty + i * 8][tx] = rna_tf32(in[(size_t)r * Cc + cx]);
    }
    __syncthreads();
    const int ox = blockIdx.y * 32 + tx;
#pragma unroll
    for (int i = 0; i < 4; i++) {
        int oy = blockIdx.x * 32 + ty + i * 8;
        out[(size_t)oy * R + ox] = t[tx][ty + i * 8];
    }
}

// ---------------------------------------------------------------------------
// 2-pass softmax: in-place exp(x - max) with rna'd write (UN-normalized),
// stores invSum[row]; normalization fused into PV epilogue.
// ---------------------------------------------------------------------------
__global__ void __launch_bounds__(256)
softmax2_kernel(float* __restrict__ S, float* __restrict__ invSum)
{
    __shared__ float red[256];
    const int tid = threadIdx.x;
    float* p = S + (size_t)blockIdx.x * SEQ;

    float m = -INFINITY;
    for (int c = tid * 4; c < SEQ; c += 1024) {
        const float4 v = *(const float4*)(p + c);
        m = fmaxf(m, fmaxf(fmaxf(v.x, v.y), fmaxf(v.z, v.w)));
    }
    red[tid] = m; __syncthreads();
    for (int s = 128; s > 0; s >>= 1) { if (tid < s) red[tid] = fmaxf(red[tid], red[tid + s]); __syncthreads(); }
    m = red[0]; __syncthreads();

    float sum = 0.0f;
    for (int c = tid * 4; c < SEQ; c += 1024) {
        float4 v = *(const float4*)(p + c);
        v.x = rna_tf32(expf(v.x - m)); v.y = rna_tf32(expf(v.y - m));
        v.z = rna_tf32(expf(v.z - m)); v.w = rna_tf32(expf(v.w - m));
        *(float4*)(p + c) = v;
        sum += v.x + v.y + v.z + v.w;
    }
    red[tid] = sum; __syncthreads();
    for (int s = 128; s > 0; s >>= 1) { if (tid < s) red[tid] += red[tid + s]; __syncthreads(); }
    if (tid == 0) invSum[blockIdx.x] = 1.0f / red[0];
}

// ---------------------------------------------------------------------------
extern "C" void kernel_launch(void* const* d_in, const int* in_sizes, int n_in,
                              void* d_out, int out_size)
{
    const float* input = (const float*)d_in[0];
    const float* Wq    = (const float*)d_in[1];
    const float* Wk    = (const float*)d_in[2];
    const float* Wv    = (const float*)d_in[3];
    float*       out   = (float*)d_out;

    __half *inCatH, *WqCTH, *WkCTH, *WvCTH, *QCatH, *KCatH;
    float *V, *VT, *S, *invS;
    cudaGetSymbolAddress((void**)&inCatH, g_inCatH);
    cudaGetSymbolAddress((void**)&WqCTH,  g_WqCTH);
    cudaGetSymbolAddress((void**)&WkCTH,  g_WkCTH);
    cudaGetSymbolAddress((void**)&WvCTH,  g_WvCTH);
    cudaGetSymbolAddress((void**)&QCatH,  g_QCatH);
    cudaGetSymbolAddress((void**)&KCatH,  g_KCatH);
    cudaGetSymbolAddress((void**)&V,      g_V);
    cudaGetSymbolAddress((void**)&VT,     g_VT);
    cudaGetSymbolAddress((void**)&S,      g_S);
    cudaGetSymbolAddress((void**)&invS,   g_invS);

    const int smemH = NSTAGE_H * STAGEH_BYTES;   // 81920
    const int smemT = 2 * STAGE_BYTES;           // 73728
    cudaFuncSetAttribute(h16_gemm, cudaFuncAttributeMaxDynamicSharedMemorySize, smemH);
    cudaFuncSetAttribute(tf32_gemm, cudaFuncAttributeMaxDynamicSharedMemorySize, smemT);

    const float scale = 1.0f / 32.0f;   // 1/sqrt(1024)
    dim3 tb(32, 8);
    dim3 gProj(DOUT / 128, SEQ / 128);
    dim3 gS(SEQ / 128, SEQ / 128);

    // 1: batched W transposes, 2: input split
    transpose_split_cat_h3<<<dim3(DOUT / 32, DIN / 32, 3), tb>>>(
        Wq, Wk, Wv, WqCTH, WkCTH, WvCTH, DIN, DOUT);
    split_cat_h<<<(SEQ * DIN / 4 + 255) / 256, 256>>>(input, inCatH, SEQ, DIN);

    // 3-5: projections (fp16 3-pass); Q/K epilogues emit split-cat layouts
    h16_gemm<<<gProj, 128, smemH>>>(inCatH, WqCTH, QCatH, DOUT, 3 * DIN,
                                    3 * DIN, 3 * DIN, 1.0f, 1);
    h16_gemm<<<gProj, 128, smemH>>>(inCatH, WkCTH, KCatH, DOUT, 3 * DIN,
                                    3 * DIN, 3 * DIN, 1.0f, 2);
    h16_gemm<<<gProj, 128, smemH>>>(inCatH, WvCTH, V, DOUT, 3 * DIN,
                                    3 * DIN, 3 * DIN, 1.0f, 0);

    // 6: scores (profiled slot): S = (QCat @ KCat^T) * scale, fp16 3-pass
    h16_gemm<<<gS, 128, smemH>>>(QCatH, KCatH, S, SEQ, 3 * DOUT,
                                 3 * DOUT, 3 * DOUT, scale, 0);

    // 7: V^T (rna), 8: softmax (2-pass, unnormalized + invSum)
    transpose_rna<<<dim3(DOUT / 32, SEQ / 32), tb>>>(V, VT, SEQ, DOUT);
    softmax2_kernel<<<SEQ, 256>>>(S, invS);

    // 9: out = (P @ V) * invSum[row], single tf32 pass
    tf32_gemm<<<gProj, 128, smemT>>>(S, VT, out, DOUT, SEQ, SEQ, SEQ, 1.0f, invS);
}

// round 9
// speedup vs baseline: 2.9321x; 1.0909x over previous
#include <cuda_runtime.h>
#include <cuda_fp16.h>
#include <math.h>
#include <stdint.h>

#define SEQ  4096
#define DIN  1024
#define DOUT 1024

// ---------------- scratch (__device__ globals, alloc-free rule) ----------------
__device__ __half g_inCatH[(size_t)SEQ * (3 * DIN)];    // [hi | hi | lo] of input
__device__ __half g_WqCTH[(size_t)DOUT * (3 * DIN)];    // [hi | lo | hi] of Wq^T
__device__ __half g_WkCTH[(size_t)DOUT * (3 * DIN)];
__device__ __half g_WvCTH[(size_t)DOUT * (3 * DIN)];
__device__ __half g_QCatH[(size_t)SEQ * (3 * DOUT)];    // [Qhi | Qhi | Qlo]
__device__ __half g_KCatH[(size_t)SEQ * (3 * DOUT)];    // [Khi | Klo | Khi]
__device__ float  g_V[(size_t)SEQ * DOUT];
__device__ __half g_VTH[(size_t)DOUT * SEQ];            // half(V^T)
__device__ float  g_S[(size_t)SEQ * SEQ];               // fp32 scores
__device__ __half g_PH[(size_t)SEQ * SEQ];              // half unnorm probs (32MB)
__device__ float  g_invS[SEQ];                          // 1/rowsum

// ---------------- helpers ----------------
#define CP_ASYNC16(saddr, gaddr) \
    asm volatile("cp.async.cg.shared.global [%0], [%1], 16;" :: "r"(saddr), "l"(gaddr))
#define CP_COMMIT() asm volatile("cp.async.commit_group;" ::: "memory")
#define CP_WAIT_GROUP(n) asm volatile("cp.async.wait_group " #n ";" ::: "memory")

__device__ __forceinline__ uint32_t smem_u32(const void* p) {
    uint32_t a;
    asm("{ .reg .u64 t; cvta.to.shared.u64 t, %1; cvt.u32.u64 %0, t; }" : "=r"(a) : "l"(p));
    return a;
}
#define LDSM_X4(r0, r1, r2, r3, addr) \
    asm volatile("ldmatrix.sync.aligned.m8n8.x4.shared.b16 {%0,%1,%2,%3}, [%4];" \
                 : "=r"(r0), "=r"(r1), "=r"(r2), "=r"(r3) : "r"(addr))

// fp16 m16n8k16 mma, fp32 accum (family-common)
__device__ __forceinline__ void mma_f16(float* d,
                                        uint32_t a0, uint32_t a1, uint32_t a2, uint32_t a3,
                                        uint32_t b0, uint32_t b1) {
    asm volatile("mma.sync.aligned.m16n8k16.row.col.f32.f16.f16.f32 "
                 "{%0,%1,%2,%3}, {%4,%5,%6,%7}, {%8,%9}, {%0,%1,%2,%3};"
                 : "+f"(d[0]), "+f"(d[1]), "+f"(d[2]), "+f"(d[3])
                 : "r"(a0), "r"(a1), "r"(a2), "r"(a3), "r"(b0), "r"(b1));
}

// ---------------------------------------------------------------------------
// fp16 GEMM: C = alpha * A[M,K] @ B[N,K]^T (half, K-major, strided)
// CTA 128x128x32, 256 thr = 8 warps (2M x 4N), warp tile 64x32 (4m x 4n).
// 4-stage cp.async pipeline, one syncthreads/iter, ldmatrix.x4 frags.
// outMode: 0 plain f32 (optional rowScale), 1 split-cat A [hi|hi|lo] (half),
//          2 split-cat B [hi|lo|hi] (half)
// ---------------------------------------------------------------------------
#define PADH 40
#define OPH_HALFS (128 * PADH)
#define OPH_BYTES (OPH_HALFS * 2)         // 10240
#define STAGEH_BYTES (2 * OPH_BYTES)      // 20480
#define NSTAGE_H 4

__global__ void __launch_bounds__(256, 2)
h16_gemm(const __half* __restrict__ A, const __half* __restrict__ B,
         void* __restrict__ Cv, int Ntot, int Kd, int lda, int ldb,
         float alpha, int outMode, const float* __restrict__ rowScale)
{
    extern __shared__ __half smh[];
    const uint32_t sbase = smem_u32(smh);

    // 8-row supertile raster swizzle for L2 reuse
    const int gx = gridDim.x, gy = gridDim.y;
    const int lin = blockIdx.y * gx + blockIdx.x;
    const int GROUP = 8;
    const int per = GROUP * gx;
    const int g = lin / per;
    const int rem = lin - g * per;
    const int rowsLeft = gy - g * GROUP;
    const int rows = (GROUP < rowsLeft) ? GROUP : rowsLeft;
    const int byi = g * GROUP + rem % rows;
    const int bxi = rem / rows;

    const int tid  = threadIdx.x;
    const int wid  = tid >> 5;
    const int lane = tid & 31;
    const int warpM = wid >> 2;           // 0..1  (64-row band)
    const int warpN = wid & 3;            // 0..3  (32-col band)
    const int gID  = lane >> 2;
    const int tig  = lane & 3;
    const int rowBase = byi * 128;
    const int colBase = bxi * 128;

    // ldmatrix per-lane tile offsets (in halfs)
    const int lt = lane >> 3;             // 0..3
    const int l7 = lane & 7;
    const int aOff = ((lt & 1) * 8 + l7) * PADH + (lt >> 1) * 8;
    const int bOff = ((lt >> 1) * 8 + l7) * PADH + (lt & 1) * 8;

    const int ldRow0 = tid >> 2;          // 0..63 (advances +64 per i)
    const int ldSeg  = tid & 3;           // 8-half segments

    auto load_stage = [&](int st, int k0) {
        const uint32_t sA = sbase + st * STAGEH_BYTES;
        const uint32_t sB = sA + OPH_BYTES;
#pragma unroll
        for (int i = 0; i < 2; i++) {
            const int row = ldRow0 + i * 64;
            CP_ASYNC16(sA + (row * PADH + ldSeg * 8) * 2,
                       A + (size_t)(rowBase + row) * lda + k0 + ldSeg * 8);
        }
#pragma unroll
        for (int i = 0; i < 2; i++) {
            const int row = ldRow0 + i * 64;
            CP_ASYNC16(sB + (row * PADH + ldSeg * 8) * 2,
                       B + (size_t)(colBase + row) * ldb + k0 + ldSeg * 8);
        }
    };

    float acc[4][4][4];
#pragma unroll
    for (int i = 0; i < 4; i++)
#pragma unroll
        for (int j = 0; j < 4; j++)
#pragma unroll
            for (int r = 0; r < 4; r++) acc[i][j][r] = 0.0f;

    const int NITER = Kd >> 5;

    load_stage(0, 0);  CP_COMMIT();
    load_stage(1, 32); CP_COMMIT();
    load_stage(2, 64); CP_COMMIT();

    for (int j = 0; j < NITER; j++) {
        CP_WAIT_GROUP(2);
        __syncthreads();
        if (j + 3 < NITER) load_stage((j + 3) & 3, (j + 3) * 32);
        CP_COMMIT();

        const uint32_t sA = sbase + (j & 3) * STAGEH_BYTES;
        const uint32_t sB = sA + OPH_BYTES;

#pragma unroll
        for (int s = 0; s < 2; s++) {
            uint32_t af[4][4];
#pragma unroll
            for (int i = 0; i < 4; i++) {
                const uint32_t addr = sA + (((warpM * 64 + i * 16) * PADH) + s * 16 + aOff) * 2;
                LDSM_X4(af[i][0], af[i][1], af[i][2], af[i][3], addr);
            }
            uint32_t bf[4][2];
#pragma unroll
            for (int p = 0; p < 2; p++) {
                const uint32_t addr = sB + (((warpN * 32 + p * 16) * PADH) + s * 16 + bOff) * 2;
                LDSM_X4(bf[2 * p][0], bf[2 * p][1], bf[2 * p + 1][0], bf[2 * p + 1][1], addr);
            }
#pragma unroll
            for (int i = 0; i < 4; i++)
#pragma unroll
                for (int jn = 0; jn < 4; jn++)
                    mma_f16(acc[i][jn], af[i][0], af[i][1], af[i][2], af[i][3],
                            bf[jn][0], bf[jn][1]);
        }
    }

    // ---- epilogue ----
#pragma unroll
    for (int i = 0; i < 4; i++) {
        const int r0 = rowBase + warpM * 64 + i * 16 + gID;
#pragma unroll
        for (int jn = 0; jn < 4; jn++) {
            const int c = colBase + warpN * 32 + jn * 8 + tig * 2;
#pragma unroll
            for (int half = 0; half < 2; half++) {
                const int r = r0 + half * 8;
                float2 v;
                v.x = acc[i][jn][half * 2 + 0];
                v.y = acc[i][jn][half * 2 + 1];
                if (outMode == 0) {
                    const float sc = rowScale ? (alpha * rowScale[r]) : alpha;
                    v.x *= sc; v.y *= sc;
                    *(float2*)((float*)Cv + (size_t)r * Ntot + c) = v;
                } else {
                    v.x *= alpha; v.y *= alpha;
                    __half2 h = __floats2half2_rn(v.x, v.y);
                    float2 hf = __half22float2(h);
                    __half2 l = __floats2half2_rn(v.x - hf.x, v.y - hf.y);
                    __half* row = (__half*)Cv + (size_t)r * (3 * Ntot) + c;
                    if (outMode == 1) {          // A-split: [hi | hi | lo]
                        *(__half2*)(row)            = h;
                        *(__half2*)(row + Ntot)     = h;
                        *(__half2*)(row + 2 * Ntot) = l;
                    } else {                     // B-split: [hi | lo | hi]
                        *(__half2*)(row)            = h;
                        *(__half2*)(row + Ntot)     = l;
                        *(__half2*)(row + 2 * Ntot) = h;
                    }
                }
            }
        }
    }
}

// ---------------------------------------------------------------------------
// split-cat to half: in[R,C] f32 -> out[R,3C] half, A mode [hi|hi|lo]
// ---------------------------------------------------------------------------
__global__ void __launch_bounds__(256)
split_cat_h(const float* __restrict__ in, __half* __restrict__ out, int R, int C)
{
    int i = blockIdx.x * 256 + threadIdx.x;
    int n4 = R * C / 4;
    if (i >= n4) return;
    float4 v = ((const float4*)in)[i];
    __half2 h0 = __floats2half2_rn(v.x, v.y);
    __half2 h1 = __floats2half2_rn(v.z, v.w);
    float2 f0 = __half22float2(h0), f1 = __half22float2(h1);
    __half2 l0 = __floats2half2_rn(v.x - f0.x, v.y - f0.y);
    __half2 l1 = __floats2half2_rn(v.z - f1.x, v.w - f1.y);
    int e = i * 4;
    int r = e / C, c = e % C;
    __half* row = out + (size_t)r * (3 * C) + c;
    *(__half2*)(row)             = h0; *(__half2*)(row + 2)         = h1;
    *(__half2*)(row + C)         = h0; *(__half2*)(row + C + 2)     = h1;
    *(__half2*)(row + 2 * C)     = l0; *(__half2*)(row + 2 * C + 2) = l1;
}

// ---------------------------------------------------------------------------
// batched transpose + split-cat half (B mode) for the 3 weight matrices
// ---------------------------------------------------------------------------
__global__ void __launch_bounds__(256)
transpose_split_cat_h3(const float* __restrict__ W0, const float* __restrict__ W1,
                       const float* __restrict__ W2,
                       __half* __restrict__ O0, __half* __restrict__ O1,
                       __half* __restrict__ O2, int R, int Cc)
{
    const float* in  = (blockIdx.z == 0) ? W0 : (blockIdx.z == 1) ? W1 : W2;
    __half*      out = (blockIdx.z == 0) ? O0 : (blockIdx.z == 1) ? O1 : O2;

    __shared__ float t[32][33];
    const int tx = threadIdx.x, ty = threadIdx.y;
    const int cx = blockIdx.x * 32 + tx;
#pragma unroll
    for (int i = 0; i < 4; i++) {
        int r = blockIdx.y * 32 + ty + i * 8;
        t[ty + i * 8][tx] = in[(size_t)r * Cc + cx];
    }
    __syncthreads();
    const int ox = blockIdx.y * 32 + tx;
#pragma unroll
    for (int i = 0; i < 4; i++) {
        int oy = blockIdx.x * 32 + ty + i * 8;
        float v = t[tx][ty + i * 8];
        __half h = __float2half_rn(v);
        __half l = __float2half_rn(v - __half2float(h));
        __half* row = out + (size_t)oy * (3 * R) + ox;
        row[0]     = h;
        row[R]     = l;
        row[2 * R] = h;
    }
}

// ---------------------------------------------------------------------------
// transpose to half: V[R,Cc] f32 -> VT[Cc,R] half (PV operand)
// ---------------------------------------------------------------------------
__global__ void __launch_bounds__(256)
transpose_h(const float* __restrict__ in, __half* __restrict__ out, int R, int Cc)
{
    __shared__ float t[32][33];
    const int tx = threadIdx.x, ty = threadIdx.y;
    const int cx = blockIdx.x * 32 + tx;
#pragma unroll
    for (int i = 0; i < 4; i++) {
        int r = blockIdx.y * 32 + ty + i * 8;
        t[ty + i * 8][tx] = in[(size_t)r * Cc + cx];
    }
    __syncthreads();
    const int ox = blockIdx.y * 32 + tx;
#pragma unroll
    for (int i = 0; i < 4; i++) {
        int oy = blockIdx.x * 32 + ty + i * 8;
        out[(size_t)oy * R + ox] = __float2half_rn(t[tx][ty + i * 8]);
    }
}

// ---------------------------------------------------------------------------
// 2-pass softmax: reads fp32 scores, writes half UN-normalized exp(x-max),
// stores invSum[row] (sum of the half-rounded values for consistency).
// ---------------------------------------------------------------------------
__global__ void __launch_bounds__(256)
softmax2h_kernel(const float* __restrict__ S, __half* __restrict__ P,
                 float* __restrict__ invSum)
{
    __shared__ float red[256];
    const int tid = threadIdx.x;
    const float* p = S + (size_t)blockIdx.x * SEQ;
    __half* q = P + (size_t)blockIdx.x * SEQ;

    float m = -INFINITY;
    for (int c = tid * 4; c < SEQ; c += 1024) {
        const float4 v = *(const float4*)(p + c);
        m = fmaxf(m, fmaxf(fmaxf(v.x, v.y), fmaxf(v.z, v.w)));
    }
    red[tid] = m; __syncthreads();
    for (int s = 128; s > 0; s >>= 1) { if (tid < s) red[tid] = fmaxf(red[tid], red[tid + s]); __syncthreads(); }
    m = red[0]; __syncthreads();

    float sum = 0.0f;
    for (int c = tid * 4; c < SEQ; c += 1024) {
        float4 v = *(const float4*)(p + c);
        __half2 e0 = __floats2half2_rn(expf(v.x - m), expf(v.y - m));
        __half2 e1 = __floats2half2_rn(expf(v.z - m), expf(v.w - m));
        *(__half2*)(q + c)     = e0;
        *(__half2*)(q + c + 2) = e1;
        float2 f0 = __half22float2(e0), f1 = __half22float2(e1);
        sum += f0.x + f0.y + f1.x + f1.y;
    }
    red[tid] = sum; __syncthreads();
    for (int s = 128; s > 0; s >>= 1) { if (tid < s) red[tid] += red[tid + s]; __syncthreads(); }
    if (tid == 0) invSum[blockIdx.x] = 1.0f / red[0];
}

// ---------------------------------------------------------------------------
extern "C" void kernel_launch(void* const* d_in, const int* in_sizes, int n_in,
                              void* d_out, int out_size)
{
    const float* input = (const float*)d_in[0];
    const float* Wq    = (const float*)d_in[1];
    const float* Wk    = (const float*)d_in[2];
    const float* Wv    = (const float*)d_in[3];
    float*       out   = (float*)d_out;

    __half *inCatH, *WqCTH, *WkCTH, *WvCTH, *QCatH, *KCatH, *VTH, *PH;
    float *V, *S, *invS;
    cudaGetSymbolAddress((void**)&inCatH, g_inCatH);
    cudaGetSymbolAddress((void**)&WqCTH,  g_WqCTH);
    cudaGetSymbolAddress((void**)&WkCTH,  g_WkCTH);
    cudaGetSymbolAddress((void**)&WvCTH,  g_WvCTH);
    cudaGetSymbolAddress((void**)&QCatH,  g_QCatH);
    cudaGetSymbolAddress((void**)&KCatH,  g_KCatH);
    cudaGetSymbolAddress((void**)&V,      g_V);
    cudaGetSymbolAddress((void**)&VTH,    g_VTH);
    cudaGetSymbolAddress((void**)&S,      g_S);
    cudaGetSymbolAddress((void**)&PH,     g_PH);
    cudaGetSymbolAddress((void**)&invS,   g_invS);

    const int smemH = NSTAGE_H * STAGEH_BYTES;   // 81920
    cudaFuncSetAttribute(h16_gemm, cudaFuncAttributeMaxDynamicSharedMemorySize, smemH);

    const float scale = 1.0f / 32.0f;   // 1/sqrt(1024)
    dim3 tb(32, 8);
    dim3 gProj(DOUT / 128, SEQ / 128);
    dim3 gS(SEQ / 128, SEQ / 128);

    // 1-2: staging
    transpose_split_cat_h3<<<dim3(DOUT / 32, DIN / 32, 3), tb>>>(
        Wq, Wk, Wv, WqCTH, WkCTH, WvCTH, DIN, DOUT);
    split_cat_h<<<(SEQ * DIN / 4 + 255) / 256, 256>>>(input, inCatH, SEQ, DIN);

    // 3-5: projections (fp16 3-pass); Q/K epilogues emit split-cat layouts
    h16_gemm<<<gProj, 256, smemH>>>(inCatH, WqCTH, QCatH, DOUT, 3 * DIN,
                                    3 * DIN, 3 * DIN, 1.0f, 1, nullptr);
    h16_gemm<<<gProj, 256, smemH>>>(inCatH, WkCTH, KCatH, DOUT, 3 * DIN,
                                    3 * DIN, 3 * DIN, 1.0f, 2, nullptr);
    h16_gemm<<<gProj, 256, smemH>>>(inCatH, WvCTH, V, DOUT, 3 * DIN,
                                    3 * DIN, 3 * DIN, 1.0f, 0, nullptr);

    // 6: scores: S = (QCat @ KCat^T) * scale, fp16 3-pass (fp32 out)
    h16_gemm<<<gS, 256, smemH>>>(QCatH, KCatH, S, SEQ, 3 * DOUT,
                                 3 * DOUT, 3 * DOUT, scale, 0, nullptr);

    // 7-8: V^T (half), softmax (fp32 -> half unnormalized + invSum)
    transpose_h<<<dim3(DOUT / 32, SEQ / 32), tb>>>(V, VTH, SEQ, DOUT);
    softmax2h_kernel<<<SEQ, 256>>>(S, PH, invS);

    // 9: out = (P @ V) * invSum[row], fp16 GEMM with fused normalization
    h16_gemm<<<gProj, 256, smemH>>>(PH, VTH, out, DOUT, SEQ,
                                    SEQ, SEQ, 1.0f, 0, invS);
}